// round 2
// baseline (speedup 1.0000x reference)
#include <cuda_runtime.h>
#include <cuda_bf16.h>
#include <math.h>

// Problem constants
#define BB 2
#define TT 2048
#define HH 2048
#define NHD 16
#define HDIM 128
#define MM (BB*TT)      // 4096 token rows
#define FF (4*HH)       // 8192

// ---------------- scratch (device globals; allocation-free) ----------------
static __device__ float g_h  [(size_t)MM*HH];   // ln1 out, reused as ln2 out
static __device__ float g_q  [(size_t)MM*HH];
static __device__ float g_k  [(size_t)MM*HH];
static __device__ float g_v  [(size_t)MM*HH];
static __device__ float g_att[(size_t)MM*HH];
static __device__ float g_x1 [(size_t)MM*HH];
static __device__ float g_ffn[(size_t)MM*FF];

// ---------------- LayerNorm: one block (256 thr) per row of 2048 -----------
__global__ __launch_bounds__(256) void ln_kernel(
    const float* __restrict__ x, const float* __restrict__ sc,
    const float* __restrict__ sh, float* __restrict__ y)
{
    const int N = HH;
    int row = blockIdx.x;
    int tid = threadIdx.x;
    const float* xr = x + (size_t)row * N;
    float vals[8];
    float s = 0.f, q = 0.f;
#pragma unroll
    for (int i = 0; i < 8; i++) {
        float v = xr[tid + i * 256];
        vals[i] = v; s += v; q += v * v;
    }
#pragma unroll
    for (int o = 16; o > 0; o >>= 1) {
        s += __shfl_xor_sync(0xffffffffu, s, o);
        q += __shfl_xor_sync(0xffffffffu, q, o);
    }
    __shared__ float ss[8], sq[8];
    __shared__ float smean, srstd;
    int warp = tid >> 5, lane = tid & 31;
    if (lane == 0) { ss[warp] = s; sq[warp] = q; }
    __syncthreads();
    if (tid == 0) {
        float S = 0.f, Q = 0.f;
#pragma unroll
        for (int i = 0; i < 8; i++) { S += ss[i]; Q += sq[i]; }
        float mean = S / N;
        float var  = Q / N - mean * mean;
        smean = mean;
        srstd = rsqrtf(var + 1e-5f);
    }
    __syncthreads();
    float mean = smean, rstd = srstd;
    float* yr = y + (size_t)row * N;
#pragma unroll
    for (int i = 0; i < 8; i++) {
        int c = tid + i * 256;
        yr[c] = sc[c] * ((vals[i] - mean) * rstd) + sh[c];
    }
}

// ---------------- tiled SGEMM with fused epilogues --------------------------
// C[M,N] = A[M,K] @ B[K,N]  (+ epilogue). All row-major. M%128==N%128==0, K%16==0.
// EPI: 0 = none, 1 = +res, 2 = gelu(+bias), 3 = +bias +res
__device__ __forceinline__ float gelu_tanh(float x) {
    float x3 = x * x * x;
    return 0.5f * x * (1.f + tanhf(0.7978845608028654f * (x + 0.044715f * x3)));
}

template <int EPI>
__global__ __launch_bounds__(256) void sgemm_kernel(
    const float* __restrict__ A, const float* __restrict__ B,
    const float* __restrict__ bias, const float* __restrict__ res,
    float* __restrict__ C, int M, int N, int K)
{
    const int BM = 128, BN = 128, BK = 16;
    __shared__ float As[BK][BM + 4];
    __shared__ float Bs[BK][BN];

    int tid = threadIdx.x;                 // 0..255
    int bm = blockIdx.y * BM;
    int bn = blockIdx.x * BN;
    int ty = tid >> 4;                     // 0..15
    int tx = tid & 15;                     // 0..15

    float acc[8][8];
#pragma unroll
    for (int i = 0; i < 8; i++)
#pragma unroll
        for (int j = 0; j < 8; j++) acc[i][j] = 0.f;

    for (int k0 = 0; k0 < K; k0 += BK) {
        // load A tile 128x16 (transposed into As)
#pragma unroll
        for (int i = 0; i < 2; i++) {
            int lin = tid + i * 256;           // 0..511
            int row = lin >> 2;                // 0..127
            int kc  = (lin & 3) * 4;           // 0,4,8,12
            float4 a = *(const float4*)(A + (size_t)(bm + row) * K + k0 + kc);
            As[kc + 0][row] = a.x;
            As[kc + 1][row] = a.y;
            As[kc + 2][row] = a.z;
            As[kc + 3][row] = a.w;
        }
        // load B tile 16x128
#pragma unroll
        for (int i = 0; i < 2; i++) {
            int lin = tid + i * 256;           // 0..511
            int kr = lin >> 5;                 // 0..15
            int nc = (lin & 31) * 4;           // 0..124
            float4 b = *(const float4*)(B + (size_t)(k0 + kr) * N + bn + nc);
            *(float4*)&Bs[kr][nc] = b;
        }
        __syncthreads();

#pragma unroll
        for (int k = 0; k < BK; k++) {
            float ra[8], rb[8];
            *(float4*)&ra[0] = *(float4*)&As[k][ty * 8];
            *(float4*)&ra[4] = *(float4*)&As[k][ty * 8 + 4];
            *(float4*)&rb[0] = *(float4*)&Bs[k][tx * 8];
            *(float4*)&rb[4] = *(float4*)&Bs[k][tx * 8 + 4];
#pragma unroll
            for (int i = 0; i < 8; i++)
#pragma unroll
                for (int j = 0; j < 8; j++)
                    acc[i][j] = fmaf(ra[i], rb[j], acc[i][j]);
        }
        __syncthreads();
    }

#pragma unroll
    for (int i = 0; i < 8; i++) {
        int row = bm + ty * 8 + i;
#pragma unroll
        for (int j = 0; j < 8; j++) {
            int col = bn + tx * 8 + j;
            size_t idx = (size_t)row * N + col;
            float v = acc[i][j];
            if (EPI == 1) v += res[idx];
            else if (EPI == 2) v = gelu_tanh(v + bias[col]);
            else if (EPI == 3) v = v + bias[col] + res[idx];
            C[idx] = v;
        }
    }
}

// ---------------- causal attention: one CTA (128 thr) per (b,h,qrow) -------
__global__ __launch_bounds__(128) void attn_kernel(
    const float* __restrict__ Q, const float* __restrict__ K,
    const float* __restrict__ V, float* __restrict__ O)
{
    int qrow = blockIdx.x;
    int bh   = blockIdx.y;
    int b = bh >> 4;
    int h = bh & 15;
    int tid = threadIdx.x;      // 0..127, owns output dim tid
    int warp = tid >> 5, lane = tid & 31;

    const float* qp = Q + ((size_t)(b * TT + qrow)) * HH + h * HDIM;
    const float* Kb = K + ((size_t)b * TT) * HH + h * HDIM;
    const float* Vb = V + ((size_t)b * TT) * HH + h * HDIM;

    __shared__ float qs[HDIM];
    __shared__ float sc[4];

    qs[tid] = qp[tid] * 0.08838834764831845f;   // 1/sqrt(128)
    __syncthreads();

    float mi = -1e30f, li = 0.f, acc = 0.f;

    for (int j0 = 0; j0 <= qrow; j0 += 4) {
        int j = j0 + warp;
        float dot = 0.f;
        if (j <= qrow) {
            const float* kr = Kb + (size_t)j * HH;
            dot = qs[lane]      * kr[lane]
                + qs[lane + 32] * kr[lane + 32]
                + qs[lane + 64] * kr[lane + 64]
                + qs[lane + 96] * kr[lane + 96];
        }
#pragma unroll
        for (int o = 16; o > 0; o >>= 1)
            dot += __shfl_xor_sync(0xffffffffu, dot, o);
        if (lane == 0) sc[warp] = (j <= qrow) ? dot : -1e30f;
        __syncthreads();

        float s0 = sc[0], s1 = sc[1], s2 = sc[2], s3 = sc[3];
        float mnew = fmaxf(mi, fmaxf(fmaxf(s0, s1), fmaxf(s2, s3)));
        float corr = __expf(mi - mnew);
        float p0 = __expf(s0 - mnew);
        float p1 = __expf(s1 - mnew);
        float p2 = __expf(s2 - mnew);
        float p3 = __expf(s3 - mnew);
        li = li * corr + p0 + p1 + p2 + p3;
        float a = acc * corr;
        a += p0 * Vb[(size_t)(j0 + 0) * HH + tid];
        if (j0 + 1 <= qrow) a += p1 * Vb[(size_t)(j0 + 1) * HH + tid];
        if (j0 + 2 <= qrow) a += p2 * Vb[(size_t)(j0 + 2) * HH + tid];
        if (j0 + 3 <= qrow) a += p3 * Vb[(size_t)(j0 + 3) * HH + tid];
        acc = a;
        mi = mnew;
        __syncthreads();
    }

    O[((size_t)(b * TT + qrow)) * HH + h * HDIM + tid] = acc / li;
}

// ---------------- launch ----------------------------------------------------
extern "C" void kernel_launch(void* const* d_in, const int* in_sizes, int n_in,
                              void* d_out, int out_size)
{
    const float* x   = (const float*)d_in[0];
    const float* wq  = (const float*)d_in[1];
    const float* wk  = (const float*)d_in[2];
    const float* wv  = (const float*)d_in[3];
    const float* wo  = (const float*)d_in[4];
    const float* ln1s = (const float*)d_in[5];
    const float* ln1b = (const float*)d_in[6];
    const float* ln2s = (const float*)d_in[7];
    const float* ln2b = (const float*)d_in[8];
    const float* w1  = (const float*)d_in[9];
    const float* b1  = (const float*)d_in[10];
    const float* w2  = (const float*)d_in[11];
    const float* b2  = (const float*)d_in[12];
    float* out = (float*)d_out;

    float *h, *q, *k, *v, *att, *x1, *ffn;
    cudaGetSymbolAddress((void**)&h,   g_h);
    cudaGetSymbolAddress((void**)&q,   g_q);
    cudaGetSymbolAddress((void**)&k,   g_k);
    cudaGetSymbolAddress((void**)&v,   g_v);
    cudaGetSymbolAddress((void**)&att, g_att);
    cudaGetSymbolAddress((void**)&x1,  g_x1);
    cudaGetSymbolAddress((void**)&ffn, g_ffn);

    dim3 gHH(HH / 128, MM / 128);    // N=2048 tiles x M=4096 tiles
    dim3 gFF(FF / 128, MM / 128);    // N=8192
    dim3 blk(256);

    // 1. LN1
    ln_kernel<<<MM, 256>>>(x, ln1s, ln1b, h);
    // 2-4. QKV projections
    sgemm_kernel<0><<<gHH, blk>>>(h, wq, nullptr, nullptr, q, MM, HH, HH);
    sgemm_kernel<0><<<gHH, blk>>>(h, wk, nullptr, nullptr, k, MM, HH, HH);
    sgemm_kernel<0><<<gHH, blk>>>(h, wv, nullptr, nullptr, v, MM, HH, HH);
    // 5. causal attention
    dim3 ga(TT, BB * NHD);
    attn_kernel<<<ga, 128>>>(q, k, v, att);
    // 6. output projection + residual
    sgemm_kernel<1><<<gHH, blk>>>(att, wo, nullptr, x, x1, MM, HH, HH);
    // 7. LN2 (reuse h)
    ln_kernel<<<MM, 256>>>(x1, ln2s, ln2b, h);
    // 8. FFN up + bias + gelu
    sgemm_kernel<2><<<gFF, blk>>>(h, w1, b1, nullptr, ffn, MM, FF, HH);
    // 9. FFN down + bias + residual -> out
    sgemm_kernel<3><<<gHH, blk>>>(ffn, w2, b2, x1, out, MM, HH, FF);
}

// round 4
// speedup vs baseline: 1.4818x; 1.4818x over previous
#include <cuda_runtime.h>
#include <cuda_bf16.h>
#include <math.h>
#include <stdint.h>

// Problem constants
#define BB 2
#define TT 2048
#define HH 2048
#define NHD 16
#define HDIM 128
#define MM (BB*TT)      // 4096 token rows
#define FF (4*HH)       // 8192

// ---------------- scratch (device globals; allocation-free) ----------------
static __device__ float g_h  [(size_t)MM*HH];   // ln1 out, reused as ln2 out
static __device__ float g_q  [(size_t)MM*HH];
static __device__ float g_k  [(size_t)MM*HH];
static __device__ float g_v  [(size_t)MM*HH];
static __device__ float g_att[(size_t)MM*HH];
static __device__ float g_x1 [(size_t)MM*HH];
static __device__ float g_ffn[(size_t)MM*FF];

// ---------------- LayerNorm: one block (256 thr) per row of 2048 -----------
__global__ __launch_bounds__(256) void ln_kernel(
    const float* __restrict__ x, const float* __restrict__ sc,
    const float* __restrict__ sh, float* __restrict__ y)
{
    const int N = HH;
    int row = blockIdx.x;
    int tid = threadIdx.x;
    const float* xr = x + (size_t)row * N;
    float vals[8];
    float s = 0.f, q = 0.f;
#pragma unroll
    for (int i = 0; i < 8; i++) {
        float v = xr[tid + i * 256];
        vals[i] = v; s += v; q += v * v;
    }
#pragma unroll
    for (int o = 16; o > 0; o >>= 1) {
        s += __shfl_xor_sync(0xffffffffu, s, o);
        q += __shfl_xor_sync(0xffffffffu, q, o);
    }
    __shared__ float ss[8], sq[8];
    __shared__ float smean, srstd;
    int warp = tid >> 5, lane = tid & 31;
    if (lane == 0) { ss[warp] = s; sq[warp] = q; }
    __syncthreads();
    if (tid == 0) {
        float S = 0.f, Q = 0.f;
#pragma unroll
        for (int i = 0; i < 8; i++) { S += ss[i]; Q += sq[i]; }
        float mean = S / N;
        float var  = Q / N - mean * mean;
        smean = mean;
        srstd = rsqrtf(var + 1e-5f);
    }
    __syncthreads();
    float mean = smean, rstd = srstd;
    float* yr = y + (size_t)row * N;
#pragma unroll
    for (int i = 0; i < 8; i++) {
        int c = tid + i * 256;
        yr[c] = sc[c] * ((vals[i] - mean) * rstd) + sh[c];
    }
}

// ---------------- tensor-core GEMM (split-bf16, 3-pass) ---------------------
// C[M,N] = A[M,K] @ B[K,N]  (+ epilogue). All row-major fp32 in/out.
// EPI: 0 = none, 1 = +res, 2 = gelu(+bias), 3 = +bias +res
__device__ __forceinline__ float gelu_tanh(float x) {
    float x3 = x * x * x;
    return 0.5f * x * (1.f + tanhf(0.7978845608028654f * (x + 0.044715f * x3)));
}

__device__ __forceinline__ uint32_t smem_u32(const void* p) {
    return (uint32_t)__cvta_generic_to_shared(p);
}

__device__ __forceinline__ void ldsm_x4(uint32_t* d, uint32_t addr) {
    asm volatile("ldmatrix.sync.aligned.m8n8.x4.shared.b16 {%0,%1,%2,%3}, [%4];"
                 : "=r"(d[0]), "=r"(d[1]), "=r"(d[2]), "=r"(d[3]) : "r"(addr));
}
__device__ __forceinline__ void ldsm_x2t(uint32_t* d, uint32_t addr) {
    asm volatile("ldmatrix.sync.aligned.m8n8.x2.trans.shared.b16 {%0,%1}, [%2];"
                 : "=r"(d[0]), "=r"(d[1]) : "r"(addr));
}
__device__ __forceinline__ void mma16816(float* c, const uint32_t* a, const uint32_t* b) {
    asm volatile("mma.sync.aligned.m16n8k16.row.col.f32.bf16.bf16.f32 "
                 "{%0,%1,%2,%3}, {%4,%5,%6,%7}, {%8,%9}, {%0,%1,%2,%3};"
                 : "+f"(c[0]), "+f"(c[1]), "+f"(c[2]), "+f"(c[3])
                 : "r"(a[0]), "r"(a[1]), "r"(a[2]), "r"(a[3]), "r"(b[0]), "r"(b[1]));
}

// split one fp32 into hi/lo bf16 (as raw ushorts)
__device__ __forceinline__ void split_bf16(float f, unsigned short& hs, unsigned short& ls) {
    __nv_bfloat16 bh = __float2bfloat16_rn(f);
    float fh = __bfloat162float(bh);
    __nv_bfloat16 bl = __float2bfloat16_rn(f - fh);
    hs = __bfloat16_as_ushort(bh);
    ls = __bfloat16_as_ushort(bl);
}

#define BM 128
#define BN 128
#define BKG 32
#define APAD 8
#define BPAD 8

template <int EPI>
__global__ __launch_bounds__(256) void bgemm_kernel(
    const float* __restrict__ A, const float* __restrict__ B,
    const float* __restrict__ bias, const float* __restrict__ res,
    float* __restrict__ C, int M, int N, int K)
{
    __shared__ unsigned short As_hi[BM][BKG + APAD];
    __shared__ unsigned short As_lo[BM][BKG + APAD];
    __shared__ unsigned short Bs_hi[BKG][BN + BPAD];
    __shared__ unsigned short Bs_lo[BKG][BN + BPAD];

    int tid = threadIdx.x;
    int bm = blockIdx.y * BM;
    int bn = blockIdx.x * BN;
    int lane = tid & 31;
    int warp = tid >> 5;
    int wm = warp & 1;        // 0..1  (64 rows each)
    int wn = warp >> 1;       // 0..3  (32 cols each)

    float acc[4][4][4];
#pragma unroll
    for (int i = 0; i < 4; i++)
#pragma unroll
        for (int j = 0; j < 4; j++)
#pragma unroll
            for (int r = 0; r < 4; r++) acc[i][j][r] = 0.f;

    float4 pa[4], pb[4];
    // prologue: load first k-chunk into registers
#pragma unroll
    for (int i = 0; i < 4; i++) {
        int lin = tid + i * 256;
        int arow = lin >> 3, ac4 = (lin & 7) * 4;
        pa[i] = *(const float4*)(A + (size_t)(bm + arow) * K + ac4);
        int bkr = lin >> 5, bc4 = (lin & 31) * 4;
        pb[i] = *(const float4*)(B + (size_t)bkr * N + bn + bc4);
    }

    const int nchunks = K / BKG;
    for (int ch = 0; ch < nchunks; ch++) {
        // convert + store registers -> split-bf16 smem
#pragma unroll
        for (int i = 0; i < 4; i++) {
            int lin = tid + i * 256;
            {
                int row = lin >> 3, c4 = (lin & 7) * 4;
                float f[4];
                f[0] = pa[i].x; f[1] = pa[i].y; f[2] = pa[i].z; f[3] = pa[i].w;
                unsigned short hs[4], ls[4];
#pragma unroll
                for (int j = 0; j < 4; j++) split_bf16(f[j], hs[j], ls[j]);
                uint32_t* dh = (uint32_t*)&As_hi[row][c4];
                uint32_t* dl = (uint32_t*)&As_lo[row][c4];
                dh[0] = (uint32_t)hs[0] | ((uint32_t)hs[1] << 16);
                dh[1] = (uint32_t)hs[2] | ((uint32_t)hs[3] << 16);
                dl[0] = (uint32_t)ls[0] | ((uint32_t)ls[1] << 16);
                dl[1] = (uint32_t)ls[2] | ((uint32_t)ls[3] << 16);
            }
            {
                int kr = lin >> 5, c4 = (lin & 31) * 4;
                float f[4];
                f[0] = pb[i].x; f[1] = pb[i].y; f[2] = pb[i].z; f[3] = pb[i].w;
                unsigned short hs[4], ls[4];
#pragma unroll
                for (int j = 0; j < 4; j++) split_bf16(f[j], hs[j], ls[j]);
                uint32_t* dh = (uint32_t*)&Bs_hi[kr][c4];
                uint32_t* dl = (uint32_t*)&Bs_lo[kr][c4];
                dh[0] = (uint32_t)hs[0] | ((uint32_t)hs[1] << 16);
                dh[1] = (uint32_t)hs[2] | ((uint32_t)hs[3] << 16);
                dl[0] = (uint32_t)ls[0] | ((uint32_t)ls[1] << 16);
                dl[1] = (uint32_t)ls[2] | ((uint32_t)ls[3] << 16);
            }
        }
        __syncthreads();

        // prefetch next chunk while computing
        if (ch + 1 < nchunks) {
            int k0 = (ch + 1) * BKG;
#pragma unroll
            for (int i = 0; i < 4; i++) {
                int lin = tid + i * 256;
                int arow = lin >> 3, ac4 = (lin & 7) * 4;
                pa[i] = *(const float4*)(A + (size_t)(bm + arow) * K + k0 + ac4);
                int bkr = lin >> 5, bc4 = (lin & 31) * 4;
                pb[i] = *(const float4*)(B + (size_t)(k0 + bkr) * N + bn + bc4);
            }
        }

        // compute: 2 k-steps of 16
#pragma unroll
        for (int ks = 0; ks < 2; ks++) {
            uint32_t a_hi[4][4], a_lo[4][4], b_hi[4][2], b_lo[4][2];
            int row_a = wm * 64 + (lane & 15);
            int kh_a = ks * 16 + ((lane >> 4) << 3);
#pragma unroll
            for (int mi = 0; mi < 4; mi++) {
                ldsm_x4(a_hi[mi], smem_u32(&As_hi[row_a + mi * 16][kh_a]));
                ldsm_x4(a_lo[mi], smem_u32(&As_lo[row_a + mi * 16][kh_a]));
            }
            int krow = ks * 16 + (lane & 15);
#pragma unroll
            for (int ni = 0; ni < 4; ni++) {
                int n0 = wn * 32 + ni * 8;
                ldsm_x2t(b_hi[ni], smem_u32(&Bs_hi[krow][n0]));
                ldsm_x2t(b_lo[ni], smem_u32(&Bs_lo[krow][n0]));
            }
#pragma unroll
            for (int mi = 0; mi < 4; mi++)
#pragma unroll
                for (int ni = 0; ni < 4; ni++) {
                    mma16816(acc[mi][ni], a_hi[mi], b_hi[ni]);
                    mma16816(acc[mi][ni], a_hi[mi], b_lo[ni]);
                    mma16816(acc[mi][ni], a_lo[mi], b_hi[ni]);
                }
        }
        __syncthreads();
    }

    // epilogue
    int g = lane >> 2, tq = lane & 3;
#pragma unroll
    for (int mi = 0; mi < 4; mi++) {
#pragma unroll
        for (int ni = 0; ni < 4; ni++) {
            int row0 = bm + wm * 64 + mi * 16 + g;
            int col0 = bn + wn * 32 + ni * 8 + tq * 2;
#pragma unroll
            for (int half = 0; half < 2; half++) {
                int row = row0 + half * 8;
                float v0 = acc[mi][ni][half * 2 + 0];
                float v1 = acc[mi][ni][half * 2 + 1];
                size_t idx = (size_t)row * N + col0;
                if (EPI == 1) { v0 += res[idx]; v1 += res[idx + 1]; }
                else if (EPI == 2) { v0 = gelu_tanh(v0 + bias[col0]); v1 = gelu_tanh(v1 + bias[col0 + 1]); }
                else if (EPI == 3) { v0 = v0 + bias[col0] + res[idx]; v1 = v1 + bias[col0 + 1] + res[idx + 1]; }
                float2 o; o.x = v0; o.y = v1;
                *(float2*)(C + idx) = o;
            }
        }
    }
}

// ---------------- causal attention: one CTA (128 thr) per (b,h,qrow) -------
__global__ __launch_bounds__(128) void attn_kernel(
    const float* __restrict__ Q, const float* __restrict__ K,
    const float* __restrict__ V, float* __restrict__ O)
{
    int qrow = blockIdx.x;
    int bh   = blockIdx.y;
    int b = bh >> 4;
    int h = bh & 15;
    int tid = threadIdx.x;
    int warp = tid >> 5, lane = tid & 31;

    const float* qp = Q + ((size_t)(b * TT + qrow)) * HH + h * HDIM;
    const float* Kb = K + ((size_t)b * TT) * HH + h * HDIM;
    const float* Vb = V + ((size_t)b * TT) * HH + h * HDIM;

    __shared__ float qs[HDIM];
    __shared__ float sc[4];

    qs[tid] = qp[tid] * 0.08838834764831845f;
    __syncthreads();

    float mi = -1e30f, li = 0.f, acc = 0.f;

    for (int j0 = 0; j0 <= qrow; j0 += 4) {
        int j = j0 + warp;
        float dot = 0.f;
        if (j <= qrow) {
            const float* kr = Kb + (size_t)j * HH;
            dot = qs[lane]      * kr[lane]
                + qs[lane + 32] * kr[lane + 32]
                + qs[lane + 64] * kr[lane + 64]
                + qs[lane + 96] * kr[lane + 96];
        }
#pragma unroll
        for (int o = 16; o > 0; o >>= 1)
            dot += __shfl_xor_sync(0xffffffffu, dot, o);
        if (lane == 0) sc[warp] = (j <= qrow) ? dot : -1e30f;
        __syncthreads();

        float s0 = sc[0], s1 = sc[1], s2 = sc[2], s3 = sc[3];
        float mnew = fmaxf(mi, fmaxf(fmaxf(s0, s1), fmaxf(s2, s3)));
        float corr = __expf(mi - mnew);
        float p0 = __expf(s0 - mnew);
        float p1 = __expf(s1 - mnew);
        float p2 = __expf(s2 - mnew);
        float p3 = __expf(s3 - mnew);
        li = li * corr + p0 + p1 + p2 + p3;
        float a = acc * corr;
        a += p0 * Vb[(size_t)(j0 + 0) * HH + tid];
        if (j0 + 1 <= qrow) a += p1 * Vb[(size_t)(j0 + 1) * HH + tid];
        if (j0 + 2 <= qrow) a += p2 * Vb[(size_t)(j0 + 2) * HH + tid];
        if (j0 + 3 <= qrow) a += p3 * Vb[(size_t)(j0 + 3) * HH + tid];
        acc = a;
        mi = mnew;
        __syncthreads();
    }

    O[((size_t)(b * TT + qrow)) * HH + h * HDIM + tid] = acc / li;
}

// ---------------- launch ----------------------------------------------------
extern "C" void kernel_launch(void* const* d_in, const int* in_sizes, int n_in,
                              void* d_out, int out_size)
{
    const float* x   = (const float*)d_in[0];
    const float* wq  = (const float*)d_in[1];
    const float* wk  = (const float*)d_in[2];
    const float* wv  = (const float*)d_in[3];
    const float* wo  = (const float*)d_in[4];
    const float* ln1s = (const float*)d_in[5];
    const float* ln1b = (const float*)d_in[6];
    const float* ln2s = (const float*)d_in[7];
    const float* ln2b = (const float*)d_in[8];
    const float* w1  = (const float*)d_in[9];
    const float* b1  = (const float*)d_in[10];
    const float* w2  = (const float*)d_in[11];
    const float* b2  = (const float*)d_in[12];
    float* out = (float*)d_out;

    float *h, *q, *k, *v, *att, *x1, *ffn;
    cudaGetSymbolAddress((void**)&h,   g_h);
    cudaGetSymbolAddress((void**)&q,   g_q);
    cudaGetSymbolAddress((void**)&k,   g_k);
    cudaGetSymbolAddress((void**)&v,   g_v);
    cudaGetSymbolAddress((void**)&att, g_att);
    cudaGetSymbolAddress((void**)&x1,  g_x1);
    cudaGetSymbolAddress((void**)&ffn, g_ffn);

    dim3 gHH(HH / BN, MM / BM);
    dim3 gFF(FF / BN, MM / BM);
    dim3 blk(256);

    ln_kernel<<<MM, 256>>>(x, ln1s, ln1b, h);
    bgemm_kernel<0><<<gHH, blk>>>(h, wq, nullptr, nullptr, q, MM, HH, HH);
    bgemm_kernel<0><<<gHH, blk>>>(h, wk, nullptr, nullptr, k, MM, HH, HH);
    bgemm_kernel<0><<<gHH, blk>>>(h, wv, nullptr, nullptr, v, MM, HH, HH);
    dim3 ga(TT, BB * NHD);
    attn_kernel<<<ga, 128>>>(q, k, v, att);
    bgemm_kernel<1><<<gHH, blk>>>(att, wo, nullptr, x, x1, MM, HH, HH);
    ln_kernel<<<MM, 256>>>(x1, ln2s, ln2b, h);
    bgemm_kernel<2><<<gFF, blk>>>(h, w1, b1, nullptr, ffn, MM, FF, HH);
    bgemm_kernel<3><<<gHH, blk>>>(ffn, w2, b2, x1, out, MM, HH, FF);
}

// round 5
// speedup vs baseline: 3.0688x; 2.0711x over previous
#include <cuda_runtime.h>
#include <cuda_bf16.h>
#include <math.h>
#include <stdint.h>

// Problem constants
#define BB 2
#define TT 2048
#define HH 2048
#define NHD 16
#define HDIM 128
#define MM (BB*TT)      // 4096 token rows
#define FF (4*HH)       // 8192

// ---------------- scratch (device globals; allocation-free) ----------------
static __device__ float g_h  [(size_t)MM*HH];
static __device__ float g_q  [(size_t)MM*HH];
static __device__ float g_k  [(size_t)MM*HH];
static __device__ float g_v  [(size_t)MM*HH];
static __device__ float g_att[(size_t)MM*HH];
static __device__ float g_x1 [(size_t)MM*HH];
static __device__ float g_ffn[(size_t)MM*FF];

// ---------------- LayerNorm ----------------
__global__ __launch_bounds__(256) void ln_kernel(
    const float* __restrict__ x, const float* __restrict__ sc,
    const float* __restrict__ sh, float* __restrict__ y)
{
    const int N = HH;
    int row = blockIdx.x;
    int tid = threadIdx.x;
    const float* xr = x + (size_t)row * N;
    float vals[8];
    float s = 0.f, q = 0.f;
#pragma unroll
    for (int i = 0; i < 8; i++) {
        float v = xr[tid + i * 256];
        vals[i] = v; s += v; q += v * v;
    }
#pragma unroll
    for (int o = 16; o > 0; o >>= 1) {
        s += __shfl_xor_sync(0xffffffffu, s, o);
        q += __shfl_xor_sync(0xffffffffu, q, o);
    }
    __shared__ float ss[8], sq[8];
    __shared__ float smean, srstd;
    int warp = tid >> 5, lane = tid & 31;
    if (lane == 0) { ss[warp] = s; sq[warp] = q; }
    __syncthreads();
    if (tid == 0) {
        float S = 0.f, Q = 0.f;
#pragma unroll
        for (int i = 0; i < 8; i++) { S += ss[i]; Q += sq[i]; }
        float mean = S / N;
        float var  = Q / N - mean * mean;
        smean = mean;
        srstd = rsqrtf(var + 1e-5f);
    }
    __syncthreads();
    float mean = smean, rstd = srstd;
    float* yr = y + (size_t)row * N;
#pragma unroll
    for (int i = 0; i < 8; i++) {
        int c = tid + i * 256;
        yr[c] = sc[c] * ((vals[i] - mean) * rstd) + sh[c];
    }
}

// ---------------- common MMA helpers ----------------
__device__ __forceinline__ float gelu_tanh(float x) {
    float x3 = x * x * x;
    return 0.5f * x * (1.f + tanhf(0.7978845608028654f * (x + 0.044715f * x3)));
}
__device__ __forceinline__ uint32_t smem_u32(const void* p) {
    return (uint32_t)__cvta_generic_to_shared(p);
}
__device__ __forceinline__ void ldsm_x4(uint32_t* d, uint32_t addr) {
    asm volatile("ldmatrix.sync.aligned.m8n8.x4.shared.b16 {%0,%1,%2,%3}, [%4];"
                 : "=r"(d[0]), "=r"(d[1]), "=r"(d[2]), "=r"(d[3]) : "r"(addr));
}
__device__ __forceinline__ void ldsm_x4t(uint32_t* d, uint32_t addr) {
    asm volatile("ldmatrix.sync.aligned.m8n8.x4.trans.shared.b16 {%0,%1,%2,%3}, [%4];"
                 : "=r"(d[0]), "=r"(d[1]), "=r"(d[2]), "=r"(d[3]) : "r"(addr));
}
__device__ __forceinline__ void ldsm_x2t(uint32_t* d, uint32_t addr) {
    asm volatile("ldmatrix.sync.aligned.m8n8.x2.trans.shared.b16 {%0,%1}, [%2];"
                 : "=r"(d[0]), "=r"(d[1]) : "r"(addr));
}
__device__ __forceinline__ void mma16816(float* c, const uint32_t* a, const uint32_t* b) {
    asm volatile("mma.sync.aligned.m16n8k16.row.col.f32.bf16.bf16.f32 "
                 "{%0,%1,%2,%3}, {%4,%5,%6,%7}, {%8,%9}, {%0,%1,%2,%3};"
                 : "+f"(c[0]), "+f"(c[1]), "+f"(c[2]), "+f"(c[3])
                 : "r"(a[0]), "r"(a[1]), "r"(a[2]), "r"(a[3]), "r"(b[0]), "r"(b[1]));
}
__device__ __forceinline__ void split_bf16(float f, unsigned short& hs, unsigned short& ls) {
    __nv_bfloat16 bh = __float2bfloat16_rn(f);
    float fh = __bfloat162float(bh);
    __nv_bfloat16 bl = __float2bfloat16_rn(f - fh);
    hs = __bfloat16_as_ushort(bh);
    ls = __bfloat16_as_ushort(bl);
}
// split two floats -> packed hi-bf16x2 and lo-bf16x2
__device__ __forceinline__ void split2pack(float f0, float f1, uint32_t& hi, uint32_t& lo) {
    unsigned short h0, l0, h1, l1;
    split_bf16(f0, h0, l0);
    split_bf16(f1, h1, l1);
    hi = (uint32_t)h0 | ((uint32_t)h1 << 16);
    lo = (uint32_t)l0 | ((uint32_t)l1 << 16);
}

// ---------------- tensor-core GEMM (split-bf16, 3-pass) ---------------------
#define BM 128
#define BN 128
#define BKG 32
#define APAD 8
#define BPAD 8

template <int EPI>
__global__ __launch_bounds__(256) void bgemm_kernel(
    const float* __restrict__ A, const float* __restrict__ B,
    const float* __restrict__ bias, const float* __restrict__ res,
    float* __restrict__ C, int M, int N, int K)
{
    __shared__ unsigned short As_hi[BM][BKG + APAD];
    __shared__ unsigned short As_lo[BM][BKG + APAD];
    __shared__ unsigned short Bs_hi[BKG][BN + BPAD];
    __shared__ unsigned short Bs_lo[BKG][BN + BPAD];

    int tid = threadIdx.x;
    int bm = blockIdx.y * BM;
    int bn = blockIdx.x * BN;
    int lane = tid & 31;
    int warp = tid >> 5;
    int wm = warp & 1;
    int wn = warp >> 1;

    float acc[4][4][4];
#pragma unroll
    for (int i = 0; i < 4; i++)
#pragma unroll
        for (int j = 0; j < 4; j++)
#pragma unroll
            for (int r = 0; r < 4; r++) acc[i][j][r] = 0.f;

    float4 pa[4], pb[4];
#pragma unroll
    for (int i = 0; i < 4; i++) {
        int lin = tid + i * 256;
        int arow = lin >> 3, ac4 = (lin & 7) * 4;
        pa[i] = *(const float4*)(A + (size_t)(bm + arow) * K + ac4);
        int bkr = lin >> 5, bc4 = (lin & 31) * 4;
        pb[i] = *(const float4*)(B + (size_t)bkr * N + bn + bc4);
    }

    const int nchunks = K / BKG;
    for (int ch = 0; ch < nchunks; ch++) {
#pragma unroll
        for (int i = 0; i < 4; i++) {
            int lin = tid + i * 256;
            {
                int row = lin >> 3, c4 = (lin & 7) * 4;
                uint32_t h0, l0, h1, l1;
                split2pack(pa[i].x, pa[i].y, h0, l0);
                split2pack(pa[i].z, pa[i].w, h1, l1);
                uint32_t* dh = (uint32_t*)&As_hi[row][c4];
                uint32_t* dl = (uint32_t*)&As_lo[row][c4];
                dh[0] = h0; dh[1] = h1; dl[0] = l0; dl[1] = l1;
            }
            {
                int kr = lin >> 5, c4 = (lin & 31) * 4;
                uint32_t h0, l0, h1, l1;
                split2pack(pb[i].x, pb[i].y, h0, l0);
                split2pack(pb[i].z, pb[i].w, h1, l1);
                uint32_t* dh = (uint32_t*)&Bs_hi[kr][c4];
                uint32_t* dl = (uint32_t*)&Bs_lo[kr][c4];
                dh[0] = h0; dh[1] = h1; dl[0] = l0; dl[1] = l1;
            }
        }
        __syncthreads();

        if (ch + 1 < nchunks) {
            int k0 = (ch + 1) * BKG;
#pragma unroll
            for (int i = 0; i < 4; i++) {
                int lin = tid + i * 256;
                int arow = lin >> 3, ac4 = (lin & 7) * 4;
                pa[i] = *(const float4*)(A + (size_t)(bm + arow) * K + k0 + ac4);
                int bkr = lin >> 5, bc4 = (lin & 31) * 4;
                pb[i] = *(const float4*)(B + (size_t)(k0 + bkr) * N + bn + bc4);
            }
        }

#pragma unroll
        for (int ks = 0; ks < 2; ks++) {
            uint32_t a_hi[4][4], a_lo[4][4], b_hi[4][2], b_lo[4][2];
            int row_a = wm * 64 + (lane & 15);
            int kh_a = ks * 16 + ((lane >> 4) << 3);
#pragma unroll
            for (int mi = 0; mi < 4; mi++) {
                ldsm_x4(a_hi[mi], smem_u32(&As_hi[row_a + mi * 16][kh_a]));
                ldsm_x4(a_lo[mi], smem_u32(&As_lo[row_a + mi * 16][kh_a]));
            }
            int krow = ks * 16 + (lane & 15);
#pragma unroll
            for (int ni = 0; ni < 4; ni++) {
                int n0 = wn * 32 + ni * 8;
                ldsm_x2t(b_hi[ni], smem_u32(&Bs_hi[krow][n0]));
                ldsm_x2t(b_lo[ni], smem_u32(&Bs_lo[krow][n0]));
            }
#pragma unroll
            for (int mi = 0; mi < 4; mi++)
#pragma unroll
                for (int ni = 0; ni < 4; ni++) {
                    mma16816(acc[mi][ni], a_hi[mi], b_hi[ni]);
                    mma16816(acc[mi][ni], a_hi[mi], b_lo[ni]);
                    mma16816(acc[mi][ni], a_lo[mi], b_hi[ni]);
                }
        }
        __syncthreads();
    }

    int g = lane >> 2, tq = lane & 3;
#pragma unroll
    for (int mi = 0; mi < 4; mi++) {
#pragma unroll
        for (int ni = 0; ni < 4; ni++) {
            int row0 = bm + wm * 64 + mi * 16 + g;
            int col0 = bn + wn * 32 + ni * 8 + tq * 2;
#pragma unroll
            for (int half = 0; half < 2; half++) {
                int row = row0 + half * 8;
                float v0 = acc[mi][ni][half * 2 + 0];
                float v1 = acc[mi][ni][half * 2 + 1];
                size_t idx = (size_t)row * N + col0;
                if (EPI == 1) { v0 += res[idx]; v1 += res[idx + 1]; }
                else if (EPI == 2) { v0 = gelu_tanh(v0 + bias[col0]); v1 = gelu_tanh(v1 + bias[col0 + 1]); }
                else if (EPI == 3) { v0 = v0 + bias[col0] + res[idx]; v1 = v1 + bias[col0 + 1] + res[idx + 1]; }
                float2 o; o.x = v0; o.y = v1;
                *(float2*)(C + idx) = o;
            }
        }
    }
}

// ---------------- flash attention (tensor-core, split-bf16) -----------------
// CTA: 128 queries x 1 head. 8 warps, each owns 16 q-rows.
// K/V in 64-key blocks, double-buffered smem. Online softmax.
#define AST 136   // smem row stride in ushorts (128 + 8 pad)

__global__ __launch_bounds__(256, 1) void fattn_kernel(
    const float* __restrict__ Qm, const float* __restrict__ Km,
    const float* __restrict__ Vm, float* __restrict__ Om)
{
    extern __shared__ unsigned short smatt[];
    unsigned short* Qh = smatt;
    unsigned short* Ql = Qh + 128 * AST;
    unsigned short* KhA = Ql + 128 * AST;       // [2][64][AST]
    unsigned short* KlA = KhA + 2 * 64 * AST;
    unsigned short* VhA = KlA + 2 * 64 * AST;
    unsigned short* VlA = VhA + 2 * 64 * AST;

    int tid = threadIdx.x, lane = tid & 31, warp = tid >> 5;
    int bh = blockIdx.x;
    int b = bh >> 4, h = bh & 15;
    int qt = 15 - (int)blockIdx.y;            // heavy tiles first

    const float* Qg = Qm + ((size_t)(b * TT + qt * 128)) * HH + h * HDIM;
    const float* Kg = Km + ((size_t)(b * TT)) * HH + h * HDIM;
    const float* Vg = Vm + ((size_t)(b * TT)) * HH + h * HDIM;

    const float rs = 0.08838834764831845f;    // 1/sqrt(128)

    // ---- load Q tile (scaled, split) ----
#pragma unroll
    for (int i = 0; i < 16; i++) {
        int lin = tid + i * 256;
        int r = lin >> 5, d4 = (lin & 31) * 4;
        float4 f = *(const float4*)(Qg + (size_t)r * HH + d4);
        uint32_t h0, l0, h1, l1;
        split2pack(f.x * rs, f.y * rs, h0, l0);
        split2pack(f.z * rs, f.w * rs, h1, l1);
        uint32_t* dh = (uint32_t*)&Qh[r * AST + d4];
        uint32_t* dl = (uint32_t*)&Ql[r * AST + d4];
        dh[0] = h0; dh[1] = h1; dl[0] = l0; dl[1] = l1;
    }

    // ---- K/V block loader (gmem -> split -> smem buffer) ----
    auto loadKV = [&](int blk, int bufI) {
        unsigned short* kh = KhA + bufI * 64 * AST;
        unsigned short* kl = KlA + bufI * 64 * AST;
        unsigned short* vh = VhA + bufI * 64 * AST;
        unsigned short* vl = VlA + bufI * 64 * AST;
        const float* kgb = Kg + (size_t)(blk * 64) * HH;
        const float* vgb = Vg + (size_t)(blk * 64) * HH;
#pragma unroll
        for (int i = 0; i < 8; i++) {
            int lin = tid + i * 256;
            int key = lin >> 5, d4 = (lin & 31) * 4;
            float4 kf = *(const float4*)(kgb + (size_t)key * HH + d4);
            float4 vf = *(const float4*)(vgb + (size_t)key * HH + d4);
            uint32_t h0, l0, h1, l1;
            split2pack(kf.x, kf.y, h0, l0);
            split2pack(kf.z, kf.w, h1, l1);
            ((uint32_t*)&kh[key * AST + d4])[0] = h0;
            ((uint32_t*)&kh[key * AST + d4])[1] = h1;
            ((uint32_t*)&kl[key * AST + d4])[0] = l0;
            ((uint32_t*)&kl[key * AST + d4])[1] = l1;
            split2pack(vf.x, vf.y, h0, l0);
            split2pack(vf.z, vf.w, h1, l1);
            ((uint32_t*)&vh[key * AST + d4])[0] = h0;
            ((uint32_t*)&vh[key * AST + d4])[1] = h1;
            ((uint32_t*)&vl[key * AST + d4])[0] = l0;
            ((uint32_t*)&vl[key * AST + d4])[1] = l1;
        }
    };

    loadKV(0, 0);
    __syncthreads();

    float o[16][4];
#pragma unroll
    for (int i = 0; i < 16; i++)
#pragma unroll
        for (int j = 0; j < 4; j++) o[i][j] = 0.f;

    float mrow0 = -1e30f, mrow1 = -1e30f;
    float lrow0 = 0.f, lrow1 = 0.f;

    int r0 = lane >> 2;
    int cbase = (lane & 3) * 2;
    int qrow0 = qt * 128 + warp * 16 + r0;
    int qrow1 = qrow0 + 8;
    int wmin = qt * 128 + warp * 16;

    const int nblocks = 2 * qt + 2;
    for (int kb = 0; kb < nblocks; kb++) {
        int buf = kb & 1;
        unsigned short* KhB = KhA + buf * 64 * AST;
        unsigned short* KlB = KlA + buf * 64 * AST;
        unsigned short* VhB = VhA + buf * 64 * AST;
        unsigned short* VlB = VlA + buf * 64 * AST;

        if (kb + 1 < nblocks) loadKV(kb + 1, buf ^ 1);

        int kbase = kb * 64;
        bool live = (kbase <= wmin + 15);   // any unmasked key for this warp?
        if (live) {
            // ---- S = Q K^T (split-bf16, 3 MMAs) ----
            float s[8][4];
#pragma unroll
            for (int i = 0; i < 8; i++)
#pragma unroll
                for (int j = 0; j < 4; j++) s[i][j] = 0.f;

#pragma unroll
            for (int ks = 0; ks < 8; ks++) {
                uint32_t ah[4], al[4];
                int qoff = (warp * 16 + (lane & 15)) * AST + ks * 16 + ((lane >> 4) << 3);
                ldsm_x4(ah, smem_u32(&Qh[qoff]));
                ldsm_x4(al, smem_u32(&Ql[qoff]));
                int nrow_off = ((lane >> 4) << 3) + (lane & 7);
                int kcol = ks * 16 + (((lane >> 3) & 1) << 3);
#pragma unroll
                for (int ntp = 0; ntp < 4; ntp++) {
                    uint32_t bhf[4], blf[4];
                    int koff = (ntp * 16 + nrow_off) * AST + kcol;
                    ldsm_x4(bhf, smem_u32(&KhB[koff]));
                    ldsm_x4(blf, smem_u32(&KlB[koff]));
                    mma16816(s[2 * ntp], ah, bhf);
                    mma16816(s[2 * ntp], ah, blf);
                    mma16816(s[2 * ntp], al, bhf);
                    mma16816(s[2 * ntp + 1], ah, bhf + 2);
                    mma16816(s[2 * ntp + 1], ah, blf + 2);
                    mma16816(s[2 * ntp + 1], al, bhf + 2);
                }
            }

            // ---- causal mask ----
            if (kbase + 63 > wmin) {
#pragma unroll
                for (int nt = 0; nt < 8; nt++) {
#pragma unroll
                    for (int j = 0; j < 2; j++) {
                        int col = kbase + nt * 8 + cbase + j;
                        if (col > qrow0) s[nt][j] = -1e30f;
                        if (col > qrow1) s[nt][2 + j] = -1e30f;
                    }
                }
            }

            // ---- online softmax ----
            float mx0 = -1e30f, mx1 = -1e30f;
#pragma unroll
            for (int nt = 0; nt < 8; nt++) {
                mx0 = fmaxf(mx0, fmaxf(s[nt][0], s[nt][1]));
                mx1 = fmaxf(mx1, fmaxf(s[nt][2], s[nt][3]));
            }
            mx0 = fmaxf(mx0, __shfl_xor_sync(0xffffffffu, mx0, 1));
            mx0 = fmaxf(mx0, __shfl_xor_sync(0xffffffffu, mx0, 2));
            mx1 = fmaxf(mx1, __shfl_xor_sync(0xffffffffu, mx1, 1));
            mx1 = fmaxf(mx1, __shfl_xor_sync(0xffffffffu, mx1, 2));
            float mn0 = fmaxf(mrow0, mx0), mn1 = fmaxf(mrow1, mx1);
            float c0 = __expf(mrow0 - mn0), c1 = __expf(mrow1 - mn1);
            mrow0 = mn0; mrow1 = mn1;
            float sum0 = 0.f, sum1 = 0.f;
#pragma unroll
            for (int nt = 0; nt < 8; nt++) {
                s[nt][0] = __expf(s[nt][0] - mn0); sum0 += s[nt][0];
                s[nt][1] = __expf(s[nt][1] - mn0); sum0 += s[nt][1];
                s[nt][2] = __expf(s[nt][2] - mn1); sum1 += s[nt][2];
                s[nt][3] = __expf(s[nt][3] - mn1); sum1 += s[nt][3];
            }
            sum0 += __shfl_xor_sync(0xffffffffu, sum0, 1);
            sum0 += __shfl_xor_sync(0xffffffffu, sum0, 2);
            sum1 += __shfl_xor_sync(0xffffffffu, sum1, 1);
            sum1 += __shfl_xor_sync(0xffffffffu, sum1, 2);
            lrow0 = lrow0 * c0 + sum0;
            lrow1 = lrow1 * c1 + sum1;
#pragma unroll
            for (int nt = 0; nt < 16; nt++) {
                o[nt][0] *= c0; o[nt][1] *= c0;
                o[nt][2] *= c1; o[nt][3] *= c1;
            }

            // ---- O += P V (split-bf16) ----
#pragma unroll
            for (int ks2 = 0; ks2 < 4; ks2++) {
                uint32_t pah[4], pal[4];
                split2pack(s[2 * ks2][0], s[2 * ks2][1], pah[0], pal[0]);
                split2pack(s[2 * ks2][2], s[2 * ks2][3], pah[1], pal[1]);
                split2pack(s[2 * ks2 + 1][0], s[2 * ks2 + 1][1], pah[2], pal[2]);
                split2pack(s[2 * ks2 + 1][2], s[2 * ks2 + 1][3], pah[3], pal[3]);
                int vrow = ks2 * 16 + (lane & 15);
                int vcol_off = (lane >> 4) << 3;
#pragma unroll
                for (int ntp = 0; ntp < 8; ntp++) {
                    uint32_t vhf[4], vlf[4];
                    int voff = vrow * AST + ntp * 16 + vcol_off;
                    ldsm_x4t(vhf, smem_u32(&VhB[voff]));
                    ldsm_x4t(vlf, smem_u32(&VlB[voff]));
                    mma16816(o[2 * ntp], pah, vhf);
                    mma16816(o[2 * ntp], pah, vlf);
                    mma16816(o[2 * ntp], pal, vhf);
                    mma16816(o[2 * ntp + 1], pah, vhf + 2);
                    mma16816(o[2 * ntp + 1], pah, vlf + 2);
                    mma16816(o[2 * ntp + 1], pal, vhf + 2);
                }
            }
        }
        __syncthreads();
    }

    // ---- write out O / l ----
    float inv0 = 1.f / lrow0, inv1 = 1.f / lrow1;
    float* Og = Om + ((size_t)(b * TT)) * HH + h * HDIM;
    int grow0 = qt * 128 + warp * 16 + r0;
#pragma unroll
    for (int nt = 0; nt < 16; nt++) {
        int col = nt * 8 + cbase;
        float2 v0; v0.x = o[nt][0] * inv0; v0.y = o[nt][1] * inv0;
        float2 v1; v1.x = o[nt][2] * inv1; v1.y = o[nt][3] * inv1;
        *(float2*)(Og + (size_t)grow0 * HH + col) = v0;
        *(float2*)(Og + (size_t)(grow0 + 8) * HH + col) = v1;
    }
}

// ---------------- launch ----------------------------------------------------
extern "C" void kernel_launch(void* const* d_in, const int* in_sizes, int n_in,
                              void* d_out, int out_size)
{
    const float* x   = (const float*)d_in[0];
    const float* wq  = (const float*)d_in[1];
    const float* wk  = (const float*)d_in[2];
    const float* wv  = (const float*)d_in[3];
    const float* wo  = (const float*)d_in[4];
    const float* ln1s = (const float*)d_in[5];
    const float* ln1b = (const float*)d_in[6];
    const float* ln2s = (const float*)d_in[7];
    const float* ln2b = (const float*)d_in[8];
    const float* w1  = (const float*)d_in[9];
    const float* b1  = (const float*)d_in[10];
    const float* w2  = (const float*)d_in[11];
    const float* b2  = (const float*)d_in[12];
    float* out = (float*)d_out;

    float *h, *q, *k, *v, *att, *x1, *ffn;
    cudaGetSymbolAddress((void**)&h,   g_h);
    cudaGetSymbolAddress((void**)&q,   g_q);
    cudaGetSymbolAddress((void**)&k,   g_k);
    cudaGetSymbolAddress((void**)&v,   g_v);
    cudaGetSymbolAddress((void**)&att, g_att);
    cudaGetSymbolAddress((void**)&x1,  g_x1);
    cudaGetSymbolAddress((void**)&ffn, g_ffn);

    dim3 gHH(HH / BN, MM / BM);
    dim3 gFF(FF / BN, MM / BM);
    dim3 blk(256);

    // flash attention dynamic smem: (2*128 + 8*64) * 136 ushorts * 2B = 208,896 B
    const int att_smem = (2 * 128 + 8 * 64) * AST * 2;
    cudaFuncSetAttribute(fattn_kernel, cudaFuncAttributeMaxDynamicSharedMemorySize, att_smem);

    ln_kernel<<<MM, 256>>>(x, ln1s, ln1b, h);
    bgemm_kernel<0><<<gHH, blk>>>(h, wq, nullptr, nullptr, q, MM, HH, HH);
    bgemm_kernel<0><<<gHH, blk>>>(h, wk, nullptr, nullptr, k, MM, HH, HH);
    bgemm_kernel<0><<<gHH, blk>>>(h, wv, nullptr, nullptr, v, MM, HH, HH);
    dim3 ga(BB * NHD, TT / 128);
    fattn_kernel<<<ga, 256, att_smem>>>(q, k, v, att);
    bgemm_kernel<1><<<gHH, blk>>>(att, wo, nullptr, x, x1, MM, HH, HH);
    ln_kernel<<<MM, 256>>>(x1, ln2s, ln2b, h);
    bgemm_kernel<2><<<gFF, blk>>>(h, w1, b1, nullptr, ffn, MM, FF, HH);
    bgemm_kernel<3><<<gHH, blk>>>(ffn, w2, b2, x1, out, MM, HH, FF);
}

// round 6
// speedup vs baseline: 3.6656x; 1.1945x over previous
#include <cuda_runtime.h>
#include <cuda_bf16.h>
#include <math.h>
#include <stdint.h>

// Problem constants
#define BB 2
#define TT 2048
#define HH 2048
#define NHD 16
#define HDIM 128
#define MM (BB*TT)      // 4096 token rows
#define FF (4*HH)       // 8192

typedef unsigned short ushort_t;

// ---------------- scratch (device globals; allocation-free) ----------------
// split-bf16 planes (hi/lo)
static __device__ ushort_t g_h_hi [(size_t)MM*HH];
static __device__ ushort_t g_h_lo [(size_t)MM*HH];
static __device__ ushort_t g_q_hi [(size_t)MM*HH];
static __device__ ushort_t g_q_lo [(size_t)MM*HH];
static __device__ ushort_t g_k_hi [(size_t)MM*HH];
static __device__ ushort_t g_k_lo [(size_t)MM*HH];
static __device__ ushort_t g_v_hi [(size_t)MM*HH];
static __device__ ushort_t g_v_lo [(size_t)MM*HH];
static __device__ ushort_t g_at_hi[(size_t)MM*HH];
static __device__ ushort_t g_at_lo[(size_t)MM*HH];
static __device__ ushort_t g_f_hi [(size_t)MM*FF];
static __device__ ushort_t g_f_lo [(size_t)MM*FF];
static __device__ float    g_x1   [(size_t)MM*HH];
// weight planes
static __device__ ushort_t g_wq_hi[(size_t)HH*HH];
static __device__ ushort_t g_wq_lo[(size_t)HH*HH];
static __device__ ushort_t g_wk_hi[(size_t)HH*HH];
static __device__ ushort_t g_wk_lo[(size_t)HH*HH];
static __device__ ushort_t g_wv_hi[(size_t)HH*HH];
static __device__ ushort_t g_wv_lo[(size_t)HH*HH];
static __device__ ushort_t g_wo_hi[(size_t)HH*HH];
static __device__ ushort_t g_wo_lo[(size_t)HH*HH];
static __device__ ushort_t g_w1_hi[(size_t)HH*FF];
static __device__ ushort_t g_w1_lo[(size_t)HH*FF];
static __device__ ushort_t g_w2_hi[(size_t)HH*FF];
static __device__ ushort_t g_w2_lo[(size_t)HH*FF];

// ---------------- helpers ----------------
__device__ __forceinline__ float gelu_tanh(float x) {
    float x3 = x * x * x;
    return 0.5f * x * (1.f + tanhf(0.7978845608028654f * (x + 0.044715f * x3)));
}
__device__ __forceinline__ uint32_t smem_u32(const void* p) {
    return (uint32_t)__cvta_generic_to_shared(p);
}
__device__ __forceinline__ void ldsm_x4(uint32_t* d, uint32_t addr) {
    asm volatile("ldmatrix.sync.aligned.m8n8.x4.shared.b16 {%0,%1,%2,%3}, [%4];"
                 : "=r"(d[0]), "=r"(d[1]), "=r"(d[2]), "=r"(d[3]) : "r"(addr));
}
__device__ __forceinline__ void ldsm_x4t(uint32_t* d, uint32_t addr) {
    asm volatile("ldmatrix.sync.aligned.m8n8.x4.trans.shared.b16 {%0,%1,%2,%3}, [%4];"
                 : "=r"(d[0]), "=r"(d[1]), "=r"(d[2]), "=r"(d[3]) : "r"(addr));
}
__device__ __forceinline__ void ldsm_x2t(uint32_t* d, uint32_t addr) {
    asm volatile("ldmatrix.sync.aligned.m8n8.x2.trans.shared.b16 {%0,%1}, [%2];"
                 : "=r"(d[0]), "=r"(d[1]) : "r"(addr));
}
__device__ __forceinline__ void mma16816(float* c, const uint32_t* a, const uint32_t* b) {
    asm volatile("mma.sync.aligned.m16n8k16.row.col.f32.bf16.bf16.f32 "
                 "{%0,%1,%2,%3}, {%4,%5,%6,%7}, {%8,%9}, {%0,%1,%2,%3};"
                 : "+f"(c[0]), "+f"(c[1]), "+f"(c[2]), "+f"(c[3])
                 : "r"(a[0]), "r"(a[1]), "r"(a[2]), "r"(a[3]), "r"(b[0]), "r"(b[1]));
}
__device__ __forceinline__ void split_bf16(float f, unsigned short& hs, unsigned short& ls) {
    __nv_bfloat16 bh = __float2bfloat16_rn(f);
    float fh = __bfloat162float(bh);
    __nv_bfloat16 bl = __float2bfloat16_rn(f - fh);
    hs = __bfloat16_as_ushort(bh);
    ls = __bfloat16_as_ushort(bl);
}
__device__ __forceinline__ void split2pack(float f0, float f1, uint32_t& hi, uint32_t& lo) {
    unsigned short h0, l0, h1, l1;
    split_bf16(f0, h0, l0);
    split_bf16(f1, h1, l1);
    hi = (uint32_t)h0 | ((uint32_t)h1 << 16);
    lo = (uint32_t)l0 | ((uint32_t)l1 << 16);
}
__device__ __forceinline__ void cpa16(uint32_t s, const void* g) {
    asm volatile("cp.async.cg.shared.global [%0], [%1], 16;" :: "r"(s), "l"(g));
}
#define CP_COMMIT() asm volatile("cp.async.commit_group;")
#define CP_WAIT(n)  asm volatile("cp.async.wait_group %0;" :: "n"(n))

// ---------------- weight splitter ----------------
__global__ __launch_bounds__(256) void wsplit_kernel(
    const float* __restrict__ w, ushort_t* __restrict__ wh, ushort_t* __restrict__ wl)
{
    size_t i4 = ((size_t)blockIdx.x * 256 + threadIdx.x) * 4;
    float4 f = *(const float4*)(w + i4);
    uint32_t h0, l0, h1, l1;
    split2pack(f.x, f.y, h0, l0);
    split2pack(f.z, f.w, h1, l1);
    uint32_t* dh = (uint32_t*)(wh + i4);
    uint32_t* dl = (uint32_t*)(wl + i4);
    dh[0] = h0; dh[1] = h1; dl[0] = l0; dl[1] = l1;
}

// ---------------- LayerNorm -> split planes ----------------
__global__ __launch_bounds__(256) void ln_kernel(
    const float* __restrict__ x, const float* __restrict__ sc,
    const float* __restrict__ sh, ushort_t* __restrict__ yh, ushort_t* __restrict__ yl)
{
    const int N = HH;
    int row = blockIdx.x;
    int tid = threadIdx.x;
    const float* xr = x + (size_t)row * N;
    float2 vals[4];
    float s = 0.f, q = 0.f;
#pragma unroll
    for (int i = 0; i < 4; i++) {
        float2 v = *(const float2*)(xr + tid * 2 + i * 512);
        vals[i] = v;
        s += v.x + v.y; q += v.x * v.x + v.y * v.y;
    }
#pragma unroll
    for (int o = 16; o > 0; o >>= 1) {
        s += __shfl_xor_sync(0xffffffffu, s, o);
        q += __shfl_xor_sync(0xffffffffu, q, o);
    }
    __shared__ float ss[8], sq[8];
    __shared__ float smean, srstd;
    int warp = tid >> 5, lane = tid & 31;
    if (lane == 0) { ss[warp] = s; sq[warp] = q; }
    __syncthreads();
    if (tid == 0) {
        float S = 0.f, Q = 0.f;
#pragma unroll
        for (int i = 0; i < 8; i++) { S += ss[i]; Q += sq[i]; }
        float mean = S / N;
        float var  = Q / N - mean * mean;
        smean = mean;
        srstd = rsqrtf(var + 1e-5f);
    }
    __syncthreads();
    float mean = smean, rstd = srstd;
#pragma unroll
    for (int i = 0; i < 4; i++) {
        int c = tid * 2 + i * 512;
        float y0 = sc[c] * ((vals[i].x - mean) * rstd) + sh[c];
        float y1 = sc[c + 1] * ((vals[i].y - mean) * rstd) + sh[c + 1];
        uint32_t h, l;
        split2pack(y0, y1, h, l);
        *(uint32_t*)(yh + (size_t)row * N + c) = h;
        *(uint32_t*)(yl + (size_t)row * N + c) = l;
    }
}

// ---------------- pipelined bf16 GEMM (pre-split operands) -------------------
// C = A @ B with A,B given as hi/lo bf16 planes. 3-MMA split accumulation.
// EPI: 0 none, 1 +res, 2 gelu(+bias), 3 +bias+res.  OSPL: 1 -> write split planes (scaled).
#define STAGES 4
#define A_ST 40     // ushort stride of A tile rows (32 + 8 pad)
#define B_ST 136    // ushort stride of B tile rows (128 + 8 pad)
#define A_TILE (128 * A_ST)
#define B_TILE (32 * B_ST)
#define STAGE_USH (2 * A_TILE + 2 * B_TILE)
#define GEMM_SMEM (STAGES * STAGE_USH * 2)

template <int EPI, int OSPL>
__global__ __launch_bounds__(256) void bgemm_kernel(
    const ushort_t* __restrict__ Ahp, const ushort_t* __restrict__ Alp,
    const ushort_t* __restrict__ Bhp, const ushort_t* __restrict__ Blp,
    const float* __restrict__ bias, const float* __restrict__ res,
    float* __restrict__ C, ushort_t* __restrict__ Chp, ushort_t* __restrict__ Clp,
    int M, int N, int K, float oscale)
{
    extern __shared__ ushort_t sm[];
    int tid = threadIdx.x;
    int bm = blockIdx.y * 128;
    int bn = blockIdx.x * 128;
    int lane = tid & 31;
    int warp = tid >> 5;
    int wm = warp & 1;
    int wn = warp >> 1;

    const int nch = K / 32;

    auto issue = [&](int ch, int st) {
        int k0 = ch * 32;
        ushort_t* a_h = sm + st * STAGE_USH;
        ushort_t* a_l = a_h + A_TILE;
        ushort_t* b_h = a_l + A_TILE;
        ushort_t* b_l = b_h + B_TILE;
#pragma unroll
        for (int i = 0; i < 2; i++) {
            int lin = tid + i * 256;
            int r = lin >> 2, c8 = (lin & 3) * 8;
            cpa16(smem_u32(a_h + r * A_ST + c8), Ahp + (size_t)(bm + r) * K + k0 + c8);
            cpa16(smem_u32(a_l + r * A_ST + c8), Alp + (size_t)(bm + r) * K + k0 + c8);
            int br = lin >> 4, bc8 = (lin & 15) * 8;
            cpa16(smem_u32(b_h + br * B_ST + bc8), Bhp + (size_t)(k0 + br) * N + bn + bc8);
            cpa16(smem_u32(b_l + br * B_ST + bc8), Blp + (size_t)(k0 + br) * N + bn + bc8);
        }
    };

    float acc[4][4][4];
#pragma unroll
    for (int i = 0; i < 4; i++)
#pragma unroll
        for (int j = 0; j < 4; j++)
#pragma unroll
            for (int r = 0; r < 4; r++) acc[i][j][r] = 0.f;

#pragma unroll
    for (int s = 0; s < STAGES - 1; s++) { issue(s, s); CP_COMMIT(); }

    for (int ch = 0; ch < nch; ch++) {
        CP_WAIT(STAGES - 2);
        __syncthreads();

        if (ch + STAGES - 1 < nch) issue(ch + STAGES - 1, (ch + STAGES - 1) % STAGES);
        CP_COMMIT();

        int st = ch % STAGES;
        ushort_t* a_h = sm + st * STAGE_USH;
        ushort_t* a_l = a_h + A_TILE;
        ushort_t* b_h = a_l + A_TILE;
        ushort_t* b_l = b_h + B_TILE;

#pragma unroll
        for (int ks = 0; ks < 2; ks++) {
            uint32_t a_hi[4][4], a_lo[4][4], b_hi[4][2], b_lo[4][2];
            int row_a = wm * 64 + (lane & 15);
            int kh_a = ks * 16 + ((lane >> 4) << 3);
#pragma unroll
            for (int mi = 0; mi < 4; mi++) {
                ldsm_x4(a_hi[mi], smem_u32(a_h + (row_a + mi * 16) * A_ST + kh_a));
                ldsm_x4(a_lo[mi], smem_u32(a_l + (row_a + mi * 16) * A_ST + kh_a));
            }
            int krow = ks * 16 + (lane & 15);
#pragma unroll
            for (int ni = 0; ni < 4; ni++) {
                int n0 = wn * 32 + ni * 8;
                ldsm_x2t(b_hi[ni], smem_u32(b_h + krow * B_ST + n0));
                ldsm_x2t(b_lo[ni], smem_u32(b_l + krow * B_ST + n0));
            }
#pragma unroll
            for (int mi = 0; mi < 4; mi++)
#pragma unroll
                for (int ni = 0; ni < 4; ni++) {
                    mma16816(acc[mi][ni], a_hi[mi], b_hi[ni]);
                    mma16816(acc[mi][ni], a_hi[mi], b_lo[ni]);
                    mma16816(acc[mi][ni], a_lo[mi], b_hi[ni]);
                }
        }
        __syncthreads();
    }

    int g = lane >> 2, tq = lane & 3;
#pragma unroll
    for (int mi = 0; mi < 4; mi++) {
#pragma unroll
        for (int ni = 0; ni < 4; ni++) {
            int row0 = bm + wm * 64 + mi * 16 + g;
            int col0 = bn + wn * 32 + ni * 8 + tq * 2;
#pragma unroll
            for (int half = 0; half < 2; half++) {
                int row = row0 + half * 8;
                float v0 = acc[mi][ni][half * 2 + 0];
                float v1 = acc[mi][ni][half * 2 + 1];
                size_t idx = (size_t)row * N + col0;
                if (EPI == 1) { v0 += res[idx]; v1 += res[idx + 1]; }
                else if (EPI == 2) { v0 = gelu_tanh(v0 + bias[col0]); v1 = gelu_tanh(v1 + bias[col0 + 1]); }
                else if (EPI == 3) { v0 = v0 + bias[col0] + res[idx]; v1 = v1 + bias[col0 + 1] + res[idx + 1]; }
                if (OSPL) {
                    uint32_t hpk, lpk;
                    split2pack(v0 * oscale, v1 * oscale, hpk, lpk);
                    *(uint32_t*)(Chp + idx) = hpk;
                    *(uint32_t*)(Clp + idx) = lpk;
                } else {
                    float2 o; o.x = v0; o.y = v1;
                    *(float2*)(C + idx) = o;
                }
            }
        }
    }
}

// ---------------- flash attention (pre-split planes, cp.async) --------------
#define AST 136

__global__ __launch_bounds__(256, 1) void fattn_kernel(
    const ushort_t* __restrict__ Qhp, const ushort_t* __restrict__ Qlp,
    const ushort_t* __restrict__ Khp, const ushort_t* __restrict__ Klp,
    const ushort_t* __restrict__ Vhp, const ushort_t* __restrict__ Vlp,
    ushort_t* __restrict__ Ohp, ushort_t* __restrict__ Olp)
{
    extern __shared__ ushort_t smatt[];
    ushort_t* Qh = smatt;
    ushort_t* Ql = Qh + 128 * AST;
    ushort_t* KhA = Ql + 128 * AST;
    ushort_t* KlA = KhA + 2 * 64 * AST;
    ushort_t* VhA = KlA + 2 * 64 * AST;
    ushort_t* VlA = VhA + 2 * 64 * AST;

    int tid = threadIdx.x, lane = tid & 31, warp = tid >> 5;
    int bh = blockIdx.x;
    int b = bh >> 4, h = bh & 15;
    int qt = 15 - (int)blockIdx.y;

    size_t qoffg = ((size_t)(b * TT + qt * 128)) * HH + h * HDIM;
    size_t kvoff = ((size_t)(b * TT)) * HH + h * HDIM;

    // Q tile (already scaled by 1/sqrt(d) in the q GEMM epilogue)
#pragma unroll
    for (int i = 0; i < 8; i++) {
        int lin = tid + i * 256;
        int r = lin >> 4, c8 = (lin & 15) * 8;
        cpa16(smem_u32(Qh + r * AST + c8), Qhp + qoffg + (size_t)r * HH + c8);
        cpa16(smem_u32(Ql + r * AST + c8), Qlp + qoffg + (size_t)r * HH + c8);
    }

    auto loadKV = [&](int blk, int bufI) {
        ushort_t* kh = KhA + bufI * 64 * AST;
        ushort_t* kl = KlA + bufI * 64 * AST;
        ushort_t* vh = VhA + bufI * 64 * AST;
        ushort_t* vl = VlA + bufI * 64 * AST;
        size_t base = kvoff + (size_t)(blk * 64) * HH;
#pragma unroll
        for (int i = 0; i < 4; i++) {
            int lin = tid + i * 256;
            int key = lin >> 4, c8 = (lin & 15) * 8;
            size_t go = base + (size_t)key * HH + c8;
            int so = key * AST + c8;
            cpa16(smem_u32(kh + so), Khp + go);
            cpa16(smem_u32(kl + so), Klp + go);
            cpa16(smem_u32(vh + so), Vhp + go);
            cpa16(smem_u32(vl + so), Vlp + go);
        }
    };

    loadKV(0, 0);
    CP_COMMIT();

    float o[16][4];
#pragma unroll
    for (int i = 0; i < 16; i++)
#pragma unroll
        for (int j = 0; j < 4; j++) o[i][j] = 0.f;

    float mrow0 = -1e30f, mrow1 = -1e30f;
    float lrow0 = 0.f, lrow1 = 0.f;

    int r0 = lane >> 2;
    int cbase = (lane & 3) * 2;
    int qrow0 = qt * 128 + warp * 16 + r0;
    int qrow1 = qrow0 + 8;
    int wmin = qt * 128 + warp * 16;

    const int nblocks = 2 * qt + 2;
    for (int kb = 0; kb < nblocks; kb++) {
        int buf = kb & 1;

        CP_WAIT(0);
        __syncthreads();

        if (kb + 1 < nblocks) loadKV(kb + 1, buf ^ 1);
        CP_COMMIT();

        ushort_t* KhB = KhA + buf * 64 * AST;
        ushort_t* KlB = KlA + buf * 64 * AST;
        ushort_t* VhB = VhA + buf * 64 * AST;
        ushort_t* VlB = VlA + buf * 64 * AST;

        int kbase = kb * 64;
        bool live = (kbase <= wmin + 15);
        if (live) {
            float s[8][4];
#pragma unroll
            for (int i = 0; i < 8; i++)
#pragma unroll
                for (int j = 0; j < 4; j++) s[i][j] = 0.f;

#pragma unroll
            for (int ks = 0; ks < 8; ks++) {
                uint32_t ah[4], al[4];
                int qoff = (warp * 16 + (lane & 15)) * AST + ks * 16 + ((lane >> 4) << 3);
                ldsm_x4(ah, smem_u32(&Qh[qoff]));
                ldsm_x4(al, smem_u32(&Ql[qoff]));
                int nrow_off = ((lane >> 4) << 3) + (lane & 7);
                int kcol = ks * 16 + (((lane >> 3) & 1) << 3);
#pragma unroll
                for (int ntp = 0; ntp < 4; ntp++) {
                    uint32_t bhf[4], blf[4];
                    int koff = (ntp * 16 + nrow_off) * AST + kcol;
                    ldsm_x4(bhf, smem_u32(&KhB[koff]));
                    ldsm_x4(blf, smem_u32(&KlB[koff]));
                    mma16816(s[2 * ntp], ah, bhf);
                    mma16816(s[2 * ntp], ah, blf);
                    mma16816(s[2 * ntp], al, bhf);
                    mma16816(s[2 * ntp + 1], ah, bhf + 2);
                    mma16816(s[2 * ntp + 1], ah, blf + 2);
                    mma16816(s[2 * ntp + 1], al, bhf + 2);
                }
            }

            if (kbase + 63 > wmin) {
#pragma unroll
                for (int nt = 0; nt < 8; nt++) {
#pragma unroll
                    for (int j = 0; j < 2; j++) {
                        int col = kbase + nt * 8 + cbase + j;
                        if (col > qrow0) s[nt][j] = -1e30f;
                        if (col > qrow1) s[nt][2 + j] = -1e30f;
                    }
                }
            }

            float mx0 = -1e30f, mx1 = -1e30f;
#pragma unroll
            for (int nt = 0; nt < 8; nt++) {
                mx0 = fmaxf(mx0, fmaxf(s[nt][0], s[nt][1]));
                mx1 = fmaxf(mx1, fmaxf(s[nt][2], s[nt][3]));
            }
            mx0 = fmaxf(mx0, __shfl_xor_sync(0xffffffffu, mx0, 1));
            mx0 = fmaxf(mx0, __shfl_xor_sync(0xffffffffu, mx0, 2));
            mx1 = fmaxf(mx1, __shfl_xor_sync(0xffffffffu, mx1, 1));
            mx1 = fmaxf(mx1, __shfl_xor_sync(0xffffffffu, mx1, 2));
            float mn0 = fmaxf(mrow0, mx0), mn1 = fmaxf(mrow1, mx1);
            float c0 = __expf(mrow0 - mn0), c1 = __expf(mrow1 - mn1);
            mrow0 = mn0; mrow1 = mn1;
            float sum0 = 0.f, sum1 = 0.f;
#pragma unroll
            for (int nt = 0; nt < 8; nt++) {
                s[nt][0] = __expf(s[nt][0] - mn0); sum0 += s[nt][0];
                s[nt][1] = __expf(s[nt][1] - mn0); sum0 += s[nt][1];
                s[nt][2] = __expf(s[nt][2] - mn1); sum1 += s[nt][2];
                s[nt][3] = __expf(s[nt][3] - mn1); sum1 += s[nt][3];
            }
            sum0 += __shfl_xor_sync(0xffffffffu, sum0, 1);
            sum0 += __shfl_xor_sync(0xffffffffu, sum0, 2);
            sum1 += __shfl_xor_sync(0xffffffffu, sum1, 1);
            sum1 += __shfl_xor_sync(0xffffffffu, sum1, 2);
            lrow0 = lrow0 * c0 + sum0;
            lrow1 = lrow1 * c1 + sum1;
#pragma unroll
            for (int nt = 0; nt < 16; nt++) {
                o[nt][0] *= c0; o[nt][1] *= c0;
                o[nt][2] *= c1; o[nt][3] *= c1;
            }

#pragma unroll
            for (int ks2 = 0; ks2 < 4; ks2++) {
                uint32_t pah[4], pal[4];
                split2pack(s[2 * ks2][0], s[2 * ks2][1], pah[0], pal[0]);
                split2pack(s[2 * ks2][2], s[2 * ks2][3], pah[1], pal[1]);
                split2pack(s[2 * ks2 + 1][0], s[2 * ks2 + 1][1], pah[2], pal[2]);
                split2pack(s[2 * ks2 + 1][2], s[2 * ks2 + 1][3], pah[3], pal[3]);
                int vrow = ks2 * 16 + (lane & 15);
                int vcol_off = (lane >> 4) << 3;
#pragma unroll
                for (int ntp = 0; ntp < 8; ntp++) {
                    uint32_t vhf[4], vlf[4];
                    int voff = vrow * AST + ntp * 16 + vcol_off;
                    ldsm_x4t(vhf, smem_u32(&VhB[voff]));
                    ldsm_x4t(vlf, smem_u32(&VlB[voff]));
                    mma16816(o[2 * ntp], pah, vhf);
                    mma16816(o[2 * ntp], pah, vlf);
                    mma16816(o[2 * ntp], pal, vhf);
                    mma16816(o[2 * ntp + 1], pah, vhf + 2);
                    mma16816(o[2 * ntp + 1], pah, vlf + 2);
                    mma16816(o[2 * ntp + 1], pal, vhf + 2);
                }
            }
        }
    }

    // write split att planes
    float inv0 = 1.f / lrow0, inv1 = 1.f / lrow1;
    size_t obase = ((size_t)(b * TT)) * HH + h * HDIM;
    int grow0 = qt * 128 + warp * 16 + r0;
#pragma unroll
    for (int nt = 0; nt < 16; nt++) {
        int col = nt * 8 + cbase;
        uint32_t hpk, lpk;
        split2pack(o[nt][0] * inv0, o[nt][1] * inv0, hpk, lpk);
        *(uint32_t*)(Ohp + obase + (size_t)grow0 * HH + col) = hpk;
        *(uint32_t*)(Olp + obase + (size_t)grow0 * HH + col) = lpk;
        split2pack(o[nt][2] * inv1, o[nt][3] * inv1, hpk, lpk);
        *(uint32_t*)(Ohp + obase + (size_t)(grow0 + 8) * HH + col) = hpk;
        *(uint32_t*)(Olp + obase + (size_t)(grow0 + 8) * HH + col) = lpk;
    }
}

// ---------------- launch ----------------------------------------------------
extern "C" void kernel_launch(void* const* d_in, const int* in_sizes, int n_in,
                              void* d_out, int out_size)
{
    const float* x   = (const float*)d_in[0];
    const float* wq  = (const float*)d_in[1];
    const float* wk  = (const float*)d_in[2];
    const float* wv  = (const float*)d_in[3];
    const float* wo  = (const float*)d_in[4];
    const float* ln1s = (const float*)d_in[5];
    const float* ln1b = (const float*)d_in[6];
    const float* ln2s = (const float*)d_in[7];
    const float* ln2b = (const float*)d_in[8];
    const float* w1  = (const float*)d_in[9];
    const float* b1  = (const float*)d_in[10];
    const float* w2  = (const float*)d_in[11];
    const float* b2  = (const float*)d_in[12];
    float* out = (float*)d_out;

    ushort_t *hh, *hl, *qh, *ql, *kh, *kl, *vh, *vl, *ath, *atl, *fh, *fl;
    ushort_t *wqh, *wql, *wkh, *wkl, *wvh, *wvl, *woh, *wol, *w1h, *w1l, *w2h, *w2l;
    float *x1;
    cudaGetSymbolAddress((void**)&hh, g_h_hi);   cudaGetSymbolAddress((void**)&hl, g_h_lo);
    cudaGetSymbolAddress((void**)&qh, g_q_hi);   cudaGetSymbolAddress((void**)&ql, g_q_lo);
    cudaGetSymbolAddress((void**)&kh, g_k_hi);   cudaGetSymbolAddress((void**)&kl, g_k_lo);
    cudaGetSymbolAddress((void**)&vh, g_v_hi);   cudaGetSymbolAddress((void**)&vl, g_v_lo);
    cudaGetSymbolAddress((void**)&ath, g_at_hi); cudaGetSymbolAddress((void**)&atl, g_at_lo);
    cudaGetSymbolAddress((void**)&fh, g_f_hi);   cudaGetSymbolAddress((void**)&fl, g_f_lo);
    cudaGetSymbolAddress((void**)&wqh, g_wq_hi); cudaGetSymbolAddress((void**)&wql, g_wq_lo);
    cudaGetSymbolAddress((void**)&wkh, g_wk_hi); cudaGetSymbolAddress((void**)&wkl, g_wk_lo);
    cudaGetSymbolAddress((void**)&wvh, g_wv_hi); cudaGetSymbolAddress((void**)&wvl, g_wv_lo);
    cudaGetSymbolAddress((void**)&woh, g_wo_hi); cudaGetSymbolAddress((void**)&wol, g_wo_lo);
    cudaGetSymbolAddress((void**)&w1h, g_w1_hi); cudaGetSymbolAddress((void**)&w1l, g_w1_lo);
    cudaGetSymbolAddress((void**)&w2h, g_w2_hi); cudaGetSymbolAddress((void**)&w2l, g_w2_lo);
    cudaGetSymbolAddress((void**)&x1, g_x1);

    // enable large dynamic smem
    cudaFuncSetAttribute(bgemm_kernel<0,1>, cudaFuncAttributeMaxDynamicSharedMemorySize, GEMM_SMEM);
    cudaFuncSetAttribute(bgemm_kernel<1,0>, cudaFuncAttributeMaxDynamicSharedMemorySize, GEMM_SMEM);
    cudaFuncSetAttribute(bgemm_kernel<2,1>, cudaFuncAttributeMaxDynamicSharedMemorySize, GEMM_SMEM);
    cudaFuncSetAttribute(bgemm_kernel<3,0>, cudaFuncAttributeMaxDynamicSharedMemorySize, GEMM_SMEM);
    const int att_smem = (2 * 128 + 8 * 64) * AST * 2;
    cudaFuncSetAttribute(fattn_kernel, cudaFuncAttributeMaxDynamicSharedMemorySize, att_smem);

    const float rs = 0.08838834764831845f;   // 1/sqrt(128)
    dim3 gHH(HH / 128, MM / 128);
    dim3 gFF(FF / 128, MM / 128);
    dim3 blk(256);

    // split weights (every launch; deterministic)
    int nW = HH * HH / 1024;
    int nW1 = HH * FF / 1024;
    wsplit_kernel<<<nW, 256>>>(wq, wqh, wql);
    wsplit_kernel<<<nW, 256>>>(wk, wkh, wkl);
    wsplit_kernel<<<nW, 256>>>(wv, wvh, wvl);
    wsplit_kernel<<<nW, 256>>>(wo, woh, wol);
    wsplit_kernel<<<nW1, 256>>>(w1, w1h, w1l);
    wsplit_kernel<<<nW1, 256>>>(w2, w2h, w2l);

    ln_kernel<<<MM, 256>>>(x, ln1s, ln1b, hh, hl);
    bgemm_kernel<0,1><<<gHH, blk, GEMM_SMEM>>>(hh, hl, wqh, wql, nullptr, nullptr, nullptr, qh, ql, MM, HH, HH, rs);
    bgemm_kernel<0,1><<<gHH, blk, GEMM_SMEM>>>(hh, hl, wkh, wkl, nullptr, nullptr, nullptr, kh, kl, MM, HH, HH, 1.f);
    bgemm_kernel<0,1><<<gHH, blk, GEMM_SMEM>>>(hh, hl, wvh, wvl, nullptr, nullptr, nullptr, vh, vl, MM, HH, HH, 1.f);
    dim3 ga(BB * NHD, TT / 128);
    fattn_kernel<<<ga, 256, att_smem>>>(qh, ql, kh, kl, vh, vl, ath, atl);
    bgemm_kernel<1,0><<<gHH, blk, GEMM_SMEM>>>(ath, atl, woh, wol, nullptr, x, x1, nullptr, nullptr, MM, HH, HH, 1.f);
    ln_kernel<<<MM, 256>>>(x1, ln2s, ln2b, hh, hl);
    bgemm_kernel<2,1><<<gFF, blk, GEMM_SMEM>>>(hh, hl, w1h, w1l, b1, nullptr, nullptr, fh, fl, MM, FF, HH, 1.f);
    bgemm_kernel<3,0><<<gHH, blk, GEMM_SMEM>>>(fh, fl, w2h, w2l, b2, x1, out, nullptr, nullptr, MM, HH, FF, 1.f);
}

// round 7
// speedup vs baseline: 3.7701x; 1.0285x over previous
#include <cuda_runtime.h>
#include <cuda_bf16.h>
#include <math.h>
#include <stdint.h>

// Problem constants
#define BB 2
#define TT 2048
#define HH 2048
#define NHD 16
#define HDIM 128
#define MM (BB*TT)      // 4096 token rows
#define FF (4*HH)       // 8192
#define H3 (3*HH)       // 6144

typedef unsigned short ushort_t;

// ---------------- scratch (device globals; allocation-free) ----------------
static __device__ ushort_t g_h_hi  [(size_t)MM*HH];
static __device__ ushort_t g_h_lo  [(size_t)MM*HH];
static __device__ ushort_t g_qkv_hi[(size_t)MM*H3];
static __device__ ushort_t g_qkv_lo[(size_t)MM*H3];
static __device__ ushort_t g_at_hi [(size_t)MM*HH];
static __device__ ushort_t g_at_lo [(size_t)MM*HH];
static __device__ ushort_t g_f_hi  [(size_t)MM*FF];
static __device__ ushort_t g_f_lo  [(size_t)MM*FF];
static __device__ float    g_x1    [(size_t)MM*HH];
// weight planes
static __device__ ushort_t g_wqkv_hi[(size_t)HH*H3];
static __device__ ushort_t g_wqkv_lo[(size_t)HH*H3];
static __device__ ushort_t g_wo_hi[(size_t)HH*HH];
static __device__ ushort_t g_wo_lo[(size_t)HH*HH];
static __device__ ushort_t g_w1_hi[(size_t)HH*FF];
static __device__ ushort_t g_w1_lo[(size_t)HH*FF];
static __device__ ushort_t g_w2_hi[(size_t)HH*FF];
static __device__ ushort_t g_w2_lo[(size_t)HH*FF];

#define RS 0.08838834764831845f   // 1/sqrt(128)

// ---------------- helpers ----------------
__device__ __forceinline__ float gelu_tanh(float x) {
    float x3 = x * x * x;
    return 0.5f * x * (1.f + tanhf(0.7978845608028654f * (x + 0.044715f * x3)));
}
__device__ __forceinline__ uint32_t smem_u32(const void* p) {
    return (uint32_t)__cvta_generic_to_shared(p);
}
__device__ __forceinline__ void ldsm_x4(uint32_t* d, uint32_t addr) {
    asm volatile("ldmatrix.sync.aligned.m8n8.x4.shared.b16 {%0,%1,%2,%3}, [%4];"
                 : "=r"(d[0]), "=r"(d[1]), "=r"(d[2]), "=r"(d[3]) : "r"(addr));
}
__device__ __forceinline__ void ldsm_x4t(uint32_t* d, uint32_t addr) {
    asm volatile("ldmatrix.sync.aligned.m8n8.x4.trans.shared.b16 {%0,%1,%2,%3}, [%4];"
                 : "=r"(d[0]), "=r"(d[1]), "=r"(d[2]), "=r"(d[3]) : "r"(addr));
}
__device__ __forceinline__ void mma16816(float* c, const uint32_t* a, const uint32_t* b) {
    asm volatile("mma.sync.aligned.m16n8k16.row.col.f32.bf16.bf16.f32 "
                 "{%0,%1,%2,%3}, {%4,%5,%6,%7}, {%8,%9}, {%0,%1,%2,%3};"
                 : "+f"(c[0]), "+f"(c[1]), "+f"(c[2]), "+f"(c[3])
                 : "r"(a[0]), "r"(a[1]), "r"(a[2]), "r"(a[3]), "r"(b[0]), "r"(b[1]));
}
__device__ __forceinline__ void split_bf16(float f, unsigned short& hs, unsigned short& ls) {
    __nv_bfloat16 bh = __float2bfloat16_rn(f);
    float fh = __bfloat162float(bh);
    __nv_bfloat16 bl = __float2bfloat16_rn(f - fh);
    hs = __bfloat16_as_ushort(bh);
    ls = __bfloat16_as_ushort(bl);
}
__device__ __forceinline__ void split2pack(float f0, float f1, uint32_t& hi, uint32_t& lo) {
    unsigned short h0, l0, h1, l1;
    split_bf16(f0, h0, l0);
    split_bf16(f1, h1, l1);
    hi = (uint32_t)h0 | ((uint32_t)h1 << 16);
    lo = (uint32_t)l0 | ((uint32_t)l1 << 16);
}
__device__ __forceinline__ void cpa16(uint32_t s, const void* g) {
    asm volatile("cp.async.cg.shared.global [%0], [%1], 16;" :: "r"(s), "l"(g));
}
#define CP_COMMIT() asm volatile("cp.async.commit_group;")
#define CP_WAIT(n)  asm volatile("cp.async.wait_group %0;" :: "n"(n))

// ---------------- weight splitters ----------------
__global__ __launch_bounds__(256) void wsplit_kernel(
    const float* __restrict__ w, ushort_t* __restrict__ wh, ushort_t* __restrict__ wl)
{
    size_t i4 = ((size_t)blockIdx.x * 256 + threadIdx.x) * 4;
    float4 f = *(const float4*)(w + i4);
    uint32_t h0, l0, h1, l1;
    split2pack(f.x, f.y, h0, l0);
    split2pack(f.z, f.w, h1, l1);
    uint32_t* dh = (uint32_t*)(wh + i4);
    uint32_t* dl = (uint32_t*)(wl + i4);
    dh[0] = h0; dh[1] = h1; dl[0] = l0; dl[1] = l1;
}

// concatenate wq|wk|wv column-wise into [HH, 3HH] split planes
__global__ __launch_bounds__(256) void wsplit_qkv_kernel(
    const float* __restrict__ wq, const float* __restrict__ wk, const float* __restrict__ wv,
    ushort_t* __restrict__ wh, ushort_t* __restrict__ wl)
{
    size_t i4 = ((size_t)blockIdx.x * 256 + threadIdx.x) * 4;
    int r = (int)(i4 / H3);
    int c = (int)(i4 % H3);
    const float* src = (c < HH) ? (wq + (size_t)r * HH + c)
                     : (c < 2 * HH) ? (wk + (size_t)r * HH + (c - HH))
                     : (wv + (size_t)r * HH + (c - 2 * HH));
    float4 f = *(const float4*)src;
    uint32_t h0, l0, h1, l1;
    split2pack(f.x, f.y, h0, l0);
    split2pack(f.z, f.w, h1, l1);
    uint32_t* dh = (uint32_t*)(wh + i4);
    uint32_t* dl = (uint32_t*)(wl + i4);
    dh[0] = h0; dh[1] = h1; dl[0] = l0; dl[1] = l1;
}

// ---------------- LayerNorm -> split planes ----------------
__global__ __launch_bounds__(256) void ln_kernel(
    const float* __restrict__ x, const float* __restrict__ sc,
    const float* __restrict__ sh, ushort_t* __restrict__ yh, ushort_t* __restrict__ yl)
{
    const int N = HH;
    int row = blockIdx.x;
    int tid = threadIdx.x;
    const float* xr = x + (size_t)row * N;
    float2 vals[4];
    float s = 0.f, q = 0.f;
#pragma unroll
    for (int i = 0; i < 4; i++) {
        float2 v = *(const float2*)(xr + tid * 2 + i * 512);
        vals[i] = v;
        s += v.x + v.y; q += v.x * v.x + v.y * v.y;
    }
#pragma unroll
    for (int o = 16; o > 0; o >>= 1) {
        s += __shfl_xor_sync(0xffffffffu, s, o);
        q += __shfl_xor_sync(0xffffffffu, q, o);
    }
    __shared__ float ss[8], sq[8];
    __shared__ float smean, srstd;
    int warp = tid >> 5, lane = tid & 31;
    if (lane == 0) { ss[warp] = s; sq[warp] = q; }
    __syncthreads();
    if (tid == 0) {
        float S = 0.f, Q = 0.f;
#pragma unroll
        for (int i = 0; i < 8; i++) { S += ss[i]; Q += sq[i]; }
        float mean = S / N;
        float var  = Q / N - mean * mean;
        smean = mean;
        srstd = rsqrtf(var + 1e-5f);
    }
    __syncthreads();
    float mean = smean, rstd = srstd;
#pragma unroll
    for (int i = 0; i < 4; i++) {
        int c = tid * 2 + i * 512;
        float y0 = sc[c] * ((vals[i].x - mean) * rstd) + sh[c];
        float y1 = sc[c + 1] * ((vals[i].y - mean) * rstd) + sh[c + 1];
        uint32_t h, l;
        split2pack(y0, y1, h, l);
        *(uint32_t*)(yh + (size_t)row * N + c) = h;
        *(uint32_t*)(yl + (size_t)row * N + c) = l;
    }
}

// ---------------- pipelined bf16 GEMM (pre-split operands) -------------------
// EPI: 0 none, 1 +res, 2 gelu(+bias), 3 +bias+res
// OSPL: 0 fp32 out, 1 split planes out (oscale), 2 split planes out qkv (rs for cols<HH)
#define STAGES 5
#define A_ST 40
#define B_ST 136
#define A_TILE (128 * A_ST)
#define B_TILE (32 * B_ST)
#define STAGE_USH (2 * A_TILE + 2 * B_TILE)
#define GEMM_SMEM (STAGES * STAGE_USH * 2)

template <int EPI, int OSPL>
__global__ __launch_bounds__(256) void bgemm_kernel(
    const ushort_t* __restrict__ Ahp, const ushort_t* __restrict__ Alp,
    const ushort_t* __restrict__ Bhp, const ushort_t* __restrict__ Blp,
    const float* __restrict__ bias, const float* __restrict__ res,
    float* __restrict__ C, ushort_t* __restrict__ Chp, ushort_t* __restrict__ Clp,
    int M, int N, int K, float oscale)
{
    extern __shared__ ushort_t sm[];
    int tid = threadIdx.x;
    int bm = blockIdx.y * 128;
    int bn = blockIdx.x * 128;
    int lane = tid & 31;
    int warp = tid >> 5;
    int wm = warp & 1;
    int wn = warp >> 1;

    const int nch = K / 32;

    auto issue = [&](int ch, int st) {
        int k0 = ch * 32;
        ushort_t* a_h = sm + st * STAGE_USH;
        ushort_t* a_l = a_h + A_TILE;
        ushort_t* b_h = a_l + A_TILE;
        ushort_t* b_l = b_h + B_TILE;
#pragma unroll
        for (int i = 0; i < 2; i++) {
            int lin = tid + i * 256;
            int r = lin >> 2, c8 = (lin & 3) * 8;
            cpa16(smem_u32(a_h + r * A_ST + c8), Ahp + (size_t)(bm + r) * K + k0 + c8);
            cpa16(smem_u32(a_l + r * A_ST + c8), Alp + (size_t)(bm + r) * K + k0 + c8);
            int br = lin >> 4, bc8 = (lin & 15) * 8;
            cpa16(smem_u32(b_h + br * B_ST + bc8), Bhp + (size_t)(k0 + br) * N + bn + bc8);
            cpa16(smem_u32(b_l + br * B_ST + bc8), Blp + (size_t)(k0 + br) * N + bn + bc8);
        }
    };

    float acc[4][4][4];
#pragma unroll
    for (int i = 0; i < 4; i++)
#pragma unroll
        for (int j = 0; j < 4; j++)
#pragma unroll
            for (int r = 0; r < 4; r++) acc[i][j][r] = 0.f;

#pragma unroll
    for (int s = 0; s < STAGES - 1; s++) { issue(s, s); CP_COMMIT(); }

    for (int ch = 0; ch < nch; ch++) {
        CP_WAIT(STAGES - 2);
        __syncthreads();

        if (ch + STAGES - 1 < nch) issue(ch + STAGES - 1, (ch + STAGES - 1) % STAGES);
        CP_COMMIT();

        int st = ch % STAGES;
        ushort_t* a_h = sm + st * STAGE_USH;
        ushort_t* a_l = a_h + A_TILE;
        ushort_t* b_h = a_l + A_TILE;
        ushort_t* b_l = b_h + B_TILE;

#pragma unroll
        for (int ks = 0; ks < 2; ks++) {
            uint32_t a_hi[4][4], a_lo[4][4], b_hi[2][4], b_lo[2][4];
            int row_a = wm * 64 + (lane & 15);
            int kh_a = ks * 16 + ((lane >> 4) << 3);
#pragma unroll
            for (int mi = 0; mi < 4; mi++) {
                ldsm_x4(a_hi[mi], smem_u32(a_h + (row_a + mi * 16) * A_ST + kh_a));
                ldsm_x4(a_lo[mi], smem_u32(a_l + (row_a + mi * 16) * A_ST + kh_a));
            }
            int krow = ks * 16 + (lane & 15);
            int bcol = (lane >> 4) << 3;
#pragma unroll
            for (int np = 0; np < 2; np++) {
                int n0 = wn * 32 + np * 16 + bcol;
                ldsm_x4t(b_hi[np], smem_u32(b_h + krow * B_ST + n0));
                ldsm_x4t(b_lo[np], smem_u32(b_l + krow * B_ST + n0));
            }
#pragma unroll
            for (int mi = 0; mi < 4; mi++)
#pragma unroll
                for (int ni = 0; ni < 4; ni++) {
                    const uint32_t* bh = &b_hi[ni >> 1][(ni & 1) * 2];
                    const uint32_t* bl = &b_lo[ni >> 1][(ni & 1) * 2];
                    mma16816(acc[mi][ni], a_hi[mi], bh);
                    mma16816(acc[mi][ni], a_hi[mi], bl);
                    mma16816(acc[mi][ni], a_lo[mi], bh);
                }
        }
    }

    int g = lane >> 2, tq = lane & 3;
#pragma unroll
    for (int mi = 0; mi < 4; mi++) {
#pragma unroll
        for (int ni = 0; ni < 4; ni++) {
            int row0 = bm + wm * 64 + mi * 16 + g;
            int col0 = bn + wn * 32 + ni * 8 + tq * 2;
#pragma unroll
            for (int half = 0; half < 2; half++) {
                int row = row0 + half * 8;
                float v0 = acc[mi][ni][half * 2 + 0];
                float v1 = acc[mi][ni][half * 2 + 1];
                size_t idx = (size_t)row * N + col0;
                if (EPI == 1) { v0 += res[idx]; v1 += res[idx + 1]; }
                else if (EPI == 2) { v0 = gelu_tanh(v0 + bias[col0]); v1 = gelu_tanh(v1 + bias[col0 + 1]); }
                else if (EPI == 3) { v0 = v0 + bias[col0] + res[idx]; v1 = v1 + bias[col0 + 1] + res[idx + 1]; }
                if (OSPL) {
                    float sc = (OSPL == 2) ? ((col0 < HH) ? RS : 1.f) : oscale;
                    uint32_t hpk, lpk;
                    split2pack(v0 * sc, v1 * sc, hpk, lpk);
                    *(uint32_t*)(Chp + idx) = hpk;
                    *(uint32_t*)(Clp + idx) = lpk;
                } else {
                    float2 o; o.x = v0; o.y = v1;
                    *(float2*)(C + idx) = o;
                }
            }
        }
    }
}

// ---------------- flash attention (reads combined qkv planes) ---------------
#define AST 136

__global__ __launch_bounds__(256, 1) void fattn_kernel(
    const ushort_t* __restrict__ QKVh, const ushort_t* __restrict__ QKVl,
    ushort_t* __restrict__ Ohp, ushort_t* __restrict__ Olp)
{
    extern __shared__ ushort_t smatt[];
    ushort_t* Qh = smatt;
    ushort_t* Ql = Qh + 128 * AST;
    ushort_t* KhA = Ql + 128 * AST;
    ushort_t* KlA = KhA + 2 * 64 * AST;
    ushort_t* VhA = KlA + 2 * 64 * AST;
    ushort_t* VlA = VhA + 2 * 64 * AST;

    int tid = threadIdx.x, lane = tid & 31, warp = tid >> 5;
    int bh = blockIdx.x;
    int b = bh >> 4, h = bh & 15;
    int qt = 15 - (int)blockIdx.y;

    size_t qoffg = ((size_t)(b * TT + qt * 128)) * H3 + h * HDIM;           // q block
    size_t koff  = ((size_t)(b * TT)) * H3 + HH + h * HDIM;                 // k block
    size_t voff  = ((size_t)(b * TT)) * H3 + 2 * HH + h * HDIM;             // v block

#pragma unroll
    for (int i = 0; i < 8; i++) {
        int lin = tid + i * 256;
        int r = lin >> 4, c8 = (lin & 15) * 8;
        cpa16(smem_u32(Qh + r * AST + c8), QKVh + qoffg + (size_t)r * H3 + c8);
        cpa16(smem_u32(Ql + r * AST + c8), QKVl + qoffg + (size_t)r * H3 + c8);
    }

    auto loadKV = [&](int blk, int bufI) {
        ushort_t* kh = KhA + bufI * 64 * AST;
        ushort_t* kl = KlA + bufI * 64 * AST;
        ushort_t* vh = VhA + bufI * 64 * AST;
        ushort_t* vl = VlA + bufI * 64 * AST;
        size_t kb = koff + (size_t)(blk * 64) * H3;
        size_t vb = voff + (size_t)(blk * 64) * H3;
#pragma unroll
        for (int i = 0; i < 4; i++) {
            int lin = tid + i * 256;
            int key = lin >> 4, c8 = (lin & 15) * 8;
            size_t stp = (size_t)key * H3 + c8;
            int so = key * AST + c8;
            cpa16(smem_u32(kh + so), QKVh + kb + stp);
            cpa16(smem_u32(kl + so), QKVl + kb + stp);
            cpa16(smem_u32(vh + so), QKVh + vb + stp);
            cpa16(smem_u32(vl + so), QKVl + vb + stp);
        }
    };

    loadKV(0, 0);
    CP_COMMIT();

    float o[16][4];
#pragma unroll
    for (int i = 0; i < 16; i++)
#pragma unroll
        for (int j = 0; j < 4; j++) o[i][j] = 0.f;

    float mrow0 = -1e30f, mrow1 = -1e30f;
    float lrow0 = 0.f, lrow1 = 0.f;

    int r0 = lane >> 2;
    int cbase = (lane & 3) * 2;
    int qrow0 = qt * 128 + warp * 16 + r0;
    int qrow1 = qrow0 + 8;
    int wmin = qt * 128 + warp * 16;

    const int nblocks = 2 * qt + 2;
    for (int kb = 0; kb < nblocks; kb++) {
        int buf = kb & 1;

        CP_WAIT(0);
        __syncthreads();

        if (kb + 1 < nblocks) loadKV(kb + 1, buf ^ 1);
        CP_COMMIT();

        ushort_t* KhB = KhA + buf * 64 * AST;
        ushort_t* KlB = KlA + buf * 64 * AST;
        ushort_t* VhB = VhA + buf * 64 * AST;
        ushort_t* VlB = VlA + buf * 64 * AST;

        int kbase = kb * 64;
        bool live = (kbase <= wmin + 15);
        if (live) {
            float s[8][4];
#pragma unroll
            for (int i = 0; i < 8; i++)
#pragma unroll
                for (int j = 0; j < 4; j++) s[i][j] = 0.f;

#pragma unroll
            for (int ks = 0; ks < 8; ks++) {
                uint32_t ah[4], al[4];
                int qoff = (warp * 16 + (lane & 15)) * AST + ks * 16 + ((lane >> 4) << 3);
                ldsm_x4(ah, smem_u32(&Qh[qoff]));
                ldsm_x4(al, smem_u32(&Ql[qoff]));
                int nrow_off = ((lane >> 4) << 3) + (lane & 7);
                int kcol = ks * 16 + (((lane >> 3) & 1) << 3);
#pragma unroll
                for (int ntp = 0; ntp < 4; ntp++) {
                    uint32_t bhf[4], blf[4];
                    int koff2 = (ntp * 16 + nrow_off) * AST + kcol;
                    ldsm_x4(bhf, smem_u32(&KhB[koff2]));
                    ldsm_x4(blf, smem_u32(&KlB[koff2]));
                    mma16816(s[2 * ntp], ah, bhf);
                    mma16816(s[2 * ntp], ah, blf);
                    mma16816(s[2 * ntp], al, bhf);
                    mma16816(s[2 * ntp + 1], ah, bhf + 2);
                    mma16816(s[2 * ntp + 1], ah, blf + 2);
                    mma16816(s[2 * ntp + 1], al, bhf + 2);
                }
            }

            if (kbase + 63 > wmin) {
#pragma unroll
                for (int nt = 0; nt < 8; nt++) {
#pragma unroll
                    for (int j = 0; j < 2; j++) {
                        int col = kbase + nt * 8 + cbase + j;
                        if (col > qrow0) s[nt][j] = -1e30f;
                        if (col > qrow1) s[nt][2 + j] = -1e30f;
                    }
                }
            }

            float mx0 = -1e30f, mx1 = -1e30f;
#pragma unroll
            for (int nt = 0; nt < 8; nt++) {
                mx0 = fmaxf(mx0, fmaxf(s[nt][0], s[nt][1]));
                mx1 = fmaxf(mx1, fmaxf(s[nt][2], s[nt][3]));
            }
            mx0 = fmaxf(mx0, __shfl_xor_sync(0xffffffffu, mx0, 1));
            mx0 = fmaxf(mx0, __shfl_xor_sync(0xffffffffu, mx0, 2));
            mx1 = fmaxf(mx1, __shfl_xor_sync(0xffffffffu, mx1, 1));
            mx1 = fmaxf(mx1, __shfl_xor_sync(0xffffffffu, mx1, 2));
            float mn0 = fmaxf(mrow0, mx0), mn1 = fmaxf(mrow1, mx1);
            float c0 = __expf(mrow0 - mn0), c1 = __expf(mrow1 - mn1);
            mrow0 = mn0; mrow1 = mn1;
            float sum0 = 0.f, sum1 = 0.f;
#pragma unroll
            for (int nt = 0; nt < 8; nt++) {
                s[nt][0] = __expf(s[nt][0] - mn0); sum0 += s[nt][0];
                s[nt][1] = __expf(s[nt][1] - mn0); sum0 += s[nt][1];
                s[nt][2] = __expf(s[nt][2] - mn1); sum1 += s[nt][2];
                s[nt][3] = __expf(s[nt][3] - mn1); sum1 += s[nt][3];
            }
            sum0 += __shfl_xor_sync(0xffffffffu, sum0, 1);
            sum0 += __shfl_xor_sync(0xffffffffu, sum0, 2);
            sum1 += __shfl_xor_sync(0xffffffffu, sum1, 1);
            sum1 += __shfl_xor_sync(0xffffffffu, sum1, 2);
            lrow0 = lrow0 * c0 + sum0;
            lrow1 = lrow1 * c1 + sum1;
#pragma unroll
            for (int nt = 0; nt < 16; nt++) {
                o[nt][0] *= c0; o[nt][1] *= c0;
                o[nt][2] *= c1; o[nt][3] *= c1;
            }

#pragma unroll
            for (int ks2 = 0; ks2 < 4; ks2++) {
                uint32_t pah[4], pal[4];
                split2pack(s[2 * ks2][0], s[2 * ks2][1], pah[0], pal[0]);
                split2pack(s[2 * ks2][2], s[2 * ks2][3], pah[1], pal[1]);
                split2pack(s[2 * ks2 + 1][0], s[2 * ks2 + 1][1], pah[2], pal[2]);
                split2pack(s[2 * ks2 + 1][2], s[2 * ks2 + 1][3], pah[3], pal[3]);
                int vrow = ks2 * 16 + (lane & 15);
                int vcol_off = (lane >> 4) << 3;
#pragma unroll
                for (int ntp = 0; ntp < 8; ntp++) {
                    uint32_t vhf[4], vlf[4];
                    int voff2 = vrow * AST + ntp * 16 + vcol_off;
                    ldsm_x4t(vhf, smem_u32(&VhB[voff2]));
                    ldsm_x4t(vlf, smem_u32(&VlB[voff2]));
                    mma16816(o[2 * ntp], pah, vhf);
                    mma16816(o[2 * ntp], pah, vlf);
                    mma16816(o[2 * ntp], pal, vhf);
                    mma16816(o[2 * ntp + 1], pah, vhf + 2);
                    mma16816(o[2 * ntp + 1], pah, vlf + 2);
                    mma16816(o[2 * ntp + 1], pal, vhf + 2);
                }
            }
        }
    }

    float inv0 = 1.f / lrow0, inv1 = 1.f / lrow1;
    size_t obase = ((size_t)(b * TT)) * HH + h * HDIM;
    int grow0 = qt * 128 + warp * 16 + r0;
#pragma unroll
    for (int nt = 0; nt < 16; nt++) {
        int col = nt * 8 + cbase;
        uint32_t hpk, lpk;
        split2pack(o[nt][0] * inv0, o[nt][1] * inv0, hpk, lpk);
        *(uint32_t*)(Ohp + obase + (size_t)grow0 * HH + col) = hpk;
        *(uint32_t*)(Olp + obase + (size_t)grow0 * HH + col) = lpk;
        split2pack(o[nt][2] * inv1, o[nt][3] * inv1, hpk, lpk);
        *(uint32_t*)(Ohp + obase + (size_t)(grow0 + 8) * HH + col) = hpk;
        *(uint32_t*)(Olp + obase + (size_t)(grow0 + 8) * HH + col) = lpk;
    }
}

// ---------------- launch ----------------------------------------------------
extern "C" void kernel_launch(void* const* d_in, const int* in_sizes, int n_in,
                              void* d_out, int out_size)
{
    const float* x   = (const float*)d_in[0];
    const float* wq  = (const float*)d_in[1];
    const float* wk  = (const float*)d_in[2];
    const float* wv  = (const float*)d_in[3];
    const float* wo  = (const float*)d_in[4];
    const float* ln1s = (const float*)d_in[5];
    const float* ln1b = (const float*)d_in[6];
    const float* ln2s = (const float*)d_in[7];
    const float* ln2b = (const float*)d_in[8];
    const float* w1  = (const float*)d_in[9];
    const float* b1  = (const float*)d_in[10];
    const float* w2  = (const float*)d_in[11];
    const float* b2  = (const float*)d_in[12];
    float* out = (float*)d_out;

    ushort_t *hh, *hl, *qkvh, *qkvl, *ath, *atl, *fh, *fl;
    ushort_t *wqkvh, *wqkvl, *woh, *wol, *w1h, *w1l, *w2h, *w2l;
    float *x1;
    cudaGetSymbolAddress((void**)&hh, g_h_hi);     cudaGetSymbolAddress((void**)&hl, g_h_lo);
    cudaGetSymbolAddress((void**)&qkvh, g_qkv_hi); cudaGetSymbolAddress((void**)&qkvl, g_qkv_lo);
    cudaGetSymbolAddress((void**)&ath, g_at_hi);   cudaGetSymbolAddress((void**)&atl, g_at_lo);
    cudaGetSymbolAddress((void**)&fh, g_f_hi);     cudaGetSymbolAddress((void**)&fl, g_f_lo);
    cudaGetSymbolAddress((void**)&wqkvh, g_wqkv_hi); cudaGetSymbolAddress((void**)&wqkvl, g_wqkv_lo);
    cudaGetSymbolAddress((void**)&woh, g_wo_hi);   cudaGetSymbolAddress((void**)&wol, g_wo_lo);
    cudaGetSymbolAddress((void**)&w1h, g_w1_hi);   cudaGetSymbolAddress((void**)&w1l, g_w1_lo);
    cudaGetSymbolAddress((void**)&w2h, g_w2_hi);   cudaGetSymbolAddress((void**)&w2l, g_w2_lo);
    cudaGetSymbolAddress((void**)&x1, g_x1);

    cudaFuncSetAttribute(bgemm_kernel<0,2>, cudaFuncAttributeMaxDynamicSharedMemorySize, GEMM_SMEM);
    cudaFuncSetAttribute(bgemm_kernel<1,0>, cudaFuncAttributeMaxDynamicSharedMemorySize, GEMM_SMEM);
    cudaFuncSetAttribute(bgemm_kernel<2,1>, cudaFuncAttributeMaxDynamicSharedMemorySize, GEMM_SMEM);
    cudaFuncSetAttribute(bgemm_kernel<3,0>, cudaFuncAttributeMaxDynamicSharedMemorySize, GEMM_SMEM);
    const int att_smem = (2 * 128 + 8 * 64) * AST * 2;
    cudaFuncSetAttribute(fattn_kernel, cudaFuncAttributeMaxDynamicSharedMemorySize, att_smem);

    dim3 gQKV(H3 / 128, MM / 128);   // 48 x 32
    dim3 gHH(HH / 128, MM / 128);
    dim3 gFF(FF / 128, MM / 128);
    dim3 blk(256);

    wsplit_qkv_kernel<<<HH * H3 / 1024, 256>>>(wq, wk, wv, wqkvh, wqkvl);
    wsplit_kernel<<<HH * HH / 1024, 256>>>(wo, woh, wol);
    wsplit_kernel<<<HH * FF / 1024, 256>>>(w1, w1h, w1l);
    wsplit_kernel<<<HH * FF / 1024, 256>>>(w2, w2h, w2l);

    ln_kernel<<<MM, 256>>>(x, ln1s, ln1b, hh, hl);
    bgemm_kernel<0,2><<<gQKV, blk, GEMM_SMEM>>>(hh, hl, wqkvh, wqkvl, nullptr, nullptr, nullptr, qkvh, qkvl, MM, H3, HH, 1.f);
    dim3 ga(BB * NHD, TT / 128);
    fattn_kernel<<<ga, 256, att_smem>>>(qkvh, qkvl, ath, atl);
    bgemm_kernel<1,0><<<gHH, blk, GEMM_SMEM>>>(ath, atl, woh, wol, nullptr, x, x1, nullptr, nullptr, MM, HH, HH, 1.f);
    ln_kernel<<<MM, 256>>>(x1, ln2s, ln2b, hh, hl);
    bgemm_kernel<2,1><<<gFF, blk, GEMM_SMEM>>>(hh, hl, w1h, w1l, b1, nullptr, nullptr, fh, fl, MM, FF, HH, 1.f);
    bgemm_kernel<3,0><<<gHH, blk, GEMM_SMEM>>>(fh, fl, w2h, w2l, b2, x1, out, nullptr, nullptr, MM, HH, FF, 1.f);
}

// round 11
// speedup vs baseline: 4.3252x; 1.1472x over previous
#include <cuda_runtime.h>
#include <cuda_bf16.h>
#include <math.h>
#include <stdint.h>

// Problem constants
#define BB 2
#define TT 2048
#define HH 2048
#define NHD 16
#define HDIM 128
#define MM (BB*TT)      // 4096 token rows
#define FF (4*HH)       // 8192
#define H3 (3*HH)       // 6144

typedef unsigned short ushort_t;

// ---------------- scratch (device globals; allocation-free) ----------------
static __device__ ushort_t g_h_hi  [(size_t)MM*HH];
static __device__ ushort_t g_h_lo  [(size_t)MM*HH];
static __device__ ushort_t g_qkv_hi[(size_t)MM*H3];
static __device__ ushort_t g_qkv_lo[(size_t)MM*H3];
static __device__ ushort_t g_at_hi [(size_t)MM*HH];
static __device__ ushort_t g_at_lo [(size_t)MM*HH];
static __device__ ushort_t g_f_hi  [(size_t)MM*FF];
static __device__ ushort_t g_f_lo  [(size_t)MM*FF];
static __device__ float    g_x1    [(size_t)MM*HH];
// weight planes [K, N] row-major (B operand via ldmatrix.trans)
static __device__ ushort_t g_wqkv_hi[(size_t)HH*H3];
static __device__ ushort_t g_wqkv_lo[(size_t)HH*H3];
static __device__ ushort_t g_wo_hi[(size_t)HH*HH];
static __device__ ushort_t g_wo_lo[(size_t)HH*HH];
static __device__ ushort_t g_w1_hi[(size_t)HH*FF];
static __device__ ushort_t g_w1_lo[(size_t)HH*FF];
static __device__ ushort_t g_w2_hi[(size_t)HH*FF];
static __device__ ushort_t g_w2_lo[(size_t)HH*FF];

#define RS 0.08838834764831845f   // 1/sqrt(128)

// ---------------- helpers ----------------
__device__ __forceinline__ float gelu_tanh(float x) {
    float x3 = x * x * x;
    return 0.5f * x * (1.f + tanhf(0.7978845608028654f * (x + 0.044715f * x3)));
}
__device__ __forceinline__ uint32_t smem_u32(const void* p) {
    return (uint32_t)__cvta_generic_to_shared(p);
}
__device__ __forceinline__ void ldsm_x4(uint32_t* d, uint32_t addr) {
    asm volatile("ldmatrix.sync.aligned.m8n8.x4.shared.b16 {%0,%1,%2,%3}, [%4];"
                 : "=r"(d[0]), "=r"(d[1]), "=r"(d[2]), "=r"(d[3]) : "r"(addr));
}
__device__ __forceinline__ void ldsm_x4t(uint32_t* d, uint32_t addr) {
    asm volatile("ldmatrix.sync.aligned.m8n8.x4.trans.shared.b16 {%0,%1,%2,%3}, [%4];"
                 : "=r"(d[0]), "=r"(d[1]), "=r"(d[2]), "=r"(d[3]) : "r"(addr));
}
__device__ __forceinline__ void mma16816(float* c, const uint32_t* a, const uint32_t* b) {
    asm volatile("mma.sync.aligned.m16n8k16.row.col.f32.bf16.bf16.f32 "
                 "{%0,%1,%2,%3}, {%4,%5,%6,%7}, {%8,%9}, {%0,%1,%2,%3};"
                 : "+f"(c[0]), "+f"(c[1]), "+f"(c[2]), "+f"(c[3])
                 : "r"(a[0]), "r"(a[1]), "r"(a[2]), "r"(a[3]), "r"(b[0]), "r"(b[1]));
}
__device__ __forceinline__ void split_bf16(float f, unsigned short& hs, unsigned short& ls) {
    __nv_bfloat16 bh = __float2bfloat16_rn(f);
    float fh = __bfloat162float(bh);
    __nv_bfloat16 bl = __float2bfloat16_rn(f - fh);
    hs = __bfloat16_as_ushort(bh);
    ls = __bfloat16_as_ushort(bl);
}
__device__ __forceinline__ void split2pack(float f0, float f1, uint32_t& hi, uint32_t& lo) {
    unsigned short h0, l0, h1, l1;
    split_bf16(f0, h0, l0);
    split_bf16(f1, h1, l1);
    hi = (uint32_t)h0 | ((uint32_t)h1 << 16);
    lo = (uint32_t)l0 | ((uint32_t)l1 << 16);
}
__device__ __forceinline__ void cpa16(uint32_t s, const void* g) {
    asm volatile("cp.async.cg.shared.global [%0], [%1], 16;" :: "r"(s), "l"(g));
}
#define CP_COMMIT() asm volatile("cp.async.commit_group;")
#define CP_WAIT(n)  asm volatile("cp.async.wait_group %0;" :: "n"(n))

// ---------------- weight splitters ----------------
__global__ __launch_bounds__(256) void wsplit_kernel(
    const float* __restrict__ w, ushort_t* __restrict__ wh, ushort_t* __restrict__ wl)
{
    size_t i4 = ((size_t)blockIdx.x * 256 + threadIdx.x) * 4;
    float4 f = *(const float4*)(w + i4);
    uint32_t h0, l0, h1, l1;
    split2pack(f.x, f.y, h0, l0);
    split2pack(f.z, f.w, h1, l1);
    uint32_t* dh = (uint32_t*)(wh + i4);
    uint32_t* dl = (uint32_t*)(wl + i4);
    dh[0] = h0; dh[1] = h1; dl[0] = l0; dl[1] = l1;
}

// concatenate wq|wk|wv column-wise into [HH, 3HH] split planes
__global__ __launch_bounds__(256) void wsplit_qkv_kernel(
    const float* __restrict__ wq, const float* __restrict__ wk, const float* __restrict__ wv,
    ushort_t* __restrict__ wh, ushort_t* __restrict__ wl)
{
    size_t i4 = ((size_t)blockIdx.x * 256 + threadIdx.x) * 4;
    int r = (int)(i4 / H3);
    int c = (int)(i4 % H3);
    const float* src = (c < HH) ? (wq + (size_t)r * HH + c)
                     : (c < 2 * HH) ? (wk + (size_t)r * HH + (c - HH))
                     : (wv + (size_t)r * HH + (c - 2 * HH));
    float4 f = *(const float4*)src;
    uint32_t h0, l0, h1, l1;
    split2pack(f.x, f.y, h0, l0);
    split2pack(f.z, f.w, h1, l1);
    uint32_t* dh = (uint32_t*)(wh + i4);
    uint32_t* dl = (uint32_t*)(wl + i4);
    dh[0] = h0; dh[1] = h1; dl[0] = l0; dl[1] = l1;
}

// ---------------- LayerNorm -> split planes ----------------
__global__ __launch_bounds__(256) void ln_kernel(
    const float* __restrict__ x, const float* __restrict__ sc,
    const float* __restrict__ sh, ushort_t* __restrict__ yh, ushort_t* __restrict__ yl)
{
    const int N = HH;
    int row = blockIdx.x;
    int tid = threadIdx.x;
    const float* xr = x + (size_t)row * N;
    float2 vals[4];
    float s = 0.f, q = 0.f;
#pragma unroll
    for (int i = 0; i < 4; i++) {
        float2 v = *(const float2*)(xr + tid * 2 + i * 512);
        vals[i] = v;
        s += v.x + v.y; q += v.x * v.x + v.y * v.y;
    }
#pragma unroll
    for (int o = 16; o > 0; o >>= 1) {
        s += __shfl_xor_sync(0xffffffffu, s, o);
        q += __shfl_xor_sync(0xffffffffu, q, o);
    }
    __shared__ float ss[8], sq[8];
    __shared__ float smean, srstd;
    int warp = tid >> 5, lane = tid & 31;
    if (lane == 0) { ss[warp] = s; sq[warp] = q; }
    __syncthreads();
    if (tid == 0) {
        float S = 0.f, Q = 0.f;
#pragma unroll
        for (int i = 0; i < 8; i++) { S += ss[i]; Q += sq[i]; }
        float mean = S / N;
        float var  = Q / N - mean * mean;
        smean = mean;
        srstd = rsqrtf(var + 1e-5f);
    }
    __syncthreads();
    float mean = smean, rstd = srstd;
#pragma unroll
    for (int i = 0; i < 4; i++) {
        int c = tid * 2 + i * 512;
        float y0 = sc[c] * ((vals[i].x - mean) * rstd) + sh[c];
        float y1 = sc[c + 1] * ((vals[i].y - mean) * rstd) + sh[c + 1];
        uint32_t h, l;
        split2pack(y0, y1, h, l);
        *(uint32_t*)(yh + (size_t)row * N + c) = h;
        *(uint32_t*)(yl + (size_t)row * N + c) = l;
    }
}

// ---------------- pipelined bf16 GEMM (pre-split operands) -------------------
// EPI: 0 none, 1 +res, 2 gelu(+bias), 3 +bias+res
// OSPL: 0 fp32 out, 1 split planes out, 2 split planes out qkv (RS for cols<HH)
#define STAGES 3
#define A_ST 40
#define B_ST 136
#define A_TILE (128 * A_ST)
#define B_TILE (32 * B_ST)
#define STAGE_USH (2 * A_TILE + 2 * B_TILE)
#define GEMM_SMEM (STAGES * STAGE_USH * 2)

template <int EPI, int OSPL>
__global__ __launch_bounds__(256, 2) void bgemm_kernel(
    const ushort_t* __restrict__ Ahp, const ushort_t* __restrict__ Alp,
    const ushort_t* __restrict__ Bhp, const ushort_t* __restrict__ Blp,
    const float* __restrict__ bias, const float* __restrict__ res,
    float* __restrict__ C, ushort_t* __restrict__ Chp, ushort_t* __restrict__ Clp,
    int M, int N, int K, float oscale)
{
    extern __shared__ ushort_t sm[];
    int tid = threadIdx.x;
    int bm = blockIdx.y * 128;
    int bn = blockIdx.x * 128;
    int lane = tid & 31;
    int warp = tid >> 5;
    int wm = warp & 1;
    int wn = warp >> 1;

    const int nch = K / 32;

    auto issue = [&](int ch, int st) {
        int k0 = ch * 32;
        ushort_t* a_h = sm + st * STAGE_USH;
        ushort_t* a_l = a_h + A_TILE;
        ushort_t* b_h = a_l + A_TILE;
        ushort_t* b_l = b_h + B_TILE;
#pragma unroll
        for (int i = 0; i < 2; i++) {
            int lin = tid + i * 256;
            int r = lin >> 2, c8 = (lin & 3) * 8;
            cpa16(smem_u32(a_h + r * A_ST + c8), Ahp + (size_t)(bm + r) * K + k0 + c8);
            cpa16(smem_u32(a_l + r * A_ST + c8), Alp + (size_t)(bm + r) * K + k0 + c8);
            int br = lin >> 4, bc8 = (lin & 15) * 8;
            cpa16(smem_u32(b_h + br * B_ST + bc8), Bhp + (size_t)(k0 + br) * N + bn + bc8);
            cpa16(smem_u32(b_l + br * B_ST + bc8), Blp + (size_t)(k0 + br) * N + bn + bc8);
        }
    };

    float acc[4][4][4];
#pragma unroll
    for (int i = 0; i < 4; i++)
#pragma unroll
        for (int j = 0; j < 4; j++)
#pragma unroll
            for (int r = 0; r < 4; r++) acc[i][j][r] = 0.f;

#pragma unroll
    for (int s = 0; s < STAGES - 1; s++) { issue(s, s); CP_COMMIT(); }

    for (int ch = 0; ch < nch; ch++) {
        CP_WAIT(STAGES - 2);
        __syncthreads();

        if (ch + STAGES - 1 < nch) issue(ch + STAGES - 1, (ch + STAGES - 1) % STAGES);
        CP_COMMIT();

        int st = ch % STAGES;
        ushort_t* a_h = sm + st * STAGE_USH;
        ushort_t* a_l = a_h + A_TILE;
        ushort_t* b_h = a_l + A_TILE;
        ushort_t* b_l = b_h + B_TILE;

#pragma unroll
        for (int ks = 0; ks < 2; ks++) {
            // B fragments first (live across the mi loop)
            uint32_t b_hi[2][4], b_lo[2][4];
            int krow = ks * 16 + (lane & 15);
            int bcol = (lane >> 4) << 3;
#pragma unroll
            for (int np = 0; np < 2; np++) {
                int n0 = wn * 32 + np * 16 + bcol;
                ldsm_x4t(b_hi[np], smem_u32(b_h + krow * B_ST + n0));
                ldsm_x4t(b_lo[np], smem_u32(b_l + krow * B_ST + n0));
            }
            int row_base = wm * 64 + (lane & 15);
            int kh_a = ks * 16 + ((lane >> 4) << 3);
            // per-mi A fragments with short live ranges
#pragma unroll
            for (int mi = 0; mi < 4; mi++) {
                uint32_t a_hi[4], a_lo[4];
                ldsm_x4(a_hi, smem_u32(a_h + (row_base + mi * 16) * A_ST + kh_a));
                ldsm_x4(a_lo, smem_u32(a_l + (row_base + mi * 16) * A_ST + kh_a));
#pragma unroll
                for (int ni = 0; ni < 4; ni++) {
                    const uint32_t* bh = &b_hi[ni >> 1][(ni & 1) * 2];
                    const uint32_t* bl = &b_lo[ni >> 1][(ni & 1) * 2];
                    mma16816(acc[mi][ni], a_hi, bh);
                    mma16816(acc[mi][ni], a_hi, bl);
                    mma16816(acc[mi][ni], a_lo, bh);
                }
            }
        }
    }

    int g = lane >> 2, tq = lane & 3;
#pragma unroll
    for (int mi = 0; mi < 4; mi++) {
#pragma unroll
        for (int ni = 0; ni < 4; ni++) {
            int row0 = bm + wm * 64 + mi * 16 + g;
            int col0 = bn + wn * 32 + ni * 8 + tq * 2;
#pragma unroll
            for (int half = 0; half < 2; half++) {
                int row = row0 + half * 8;
                float v0 = acc[mi][ni][half * 2 + 0];
                float v1 = acc[mi][ni][half * 2 + 1];
                size_t idx = (size_t)row * N + col0;
                if (EPI == 1) { v0 += res[idx]; v1 += res[idx + 1]; }
                else if (EPI == 2) { v0 = gelu_tanh(v0 + bias[col0]); v1 = gelu_tanh(v1 + bias[col0 + 1]); }
                else if (EPI == 3) { v0 = v0 + bias[col0] + res[idx]; v1 = v1 + bias[col0 + 1] + res[idx + 1]; }
                if (OSPL) {
                    float sc = (OSPL == 2) ? ((col0 < HH) ? RS : 1.f) : oscale;
                    uint32_t hpk, lpk;
                    split2pack(v0 * sc, v1 * sc, hpk, lpk);
                    *(uint32_t*)(Chp + idx) = hpk;
                    *(uint32_t*)(Clp + idx) = lpk;
                } else {
                    float2 o; o.x = v0; o.y = v1;
                    *(float2*)(C + idx) = o;
                }
            }
        }
    }
}

// ---------------- flash attention (reads combined qkv planes) ---------------
#define AST 136

__global__ __launch_bounds__(256, 1) void fattn_kernel(
    const ushort_t* __restrict__ QKVh, const ushort_t* __restrict__ QKVl,
    ushort_t* __restrict__ Ohp, ushort_t* __restrict__ Olp)
{
    extern __shared__ ushort_t smatt[];
    ushort_t* Qh = smatt;
    ushort_t* Ql = Qh + 128 * AST;
    ushort_t* KhA = Ql + 128 * AST;
    ushort_t* KlA = KhA + 2 * 64 * AST;
    ushort_t* VhA = KlA + 2 * 64 * AST;
    ushort_t* VlA = VhA + 2 * 64 * AST;

    int tid = threadIdx.x, lane = tid & 31, warp = tid >> 5;
    int bh = blockIdx.x;
    int b = bh >> 4, h = bh & 15;
    int qt = 15 - (int)blockIdx.y;

    size_t qoffg = ((size_t)(b * TT + qt * 128)) * H3 + h * HDIM;
    size_t koff  = ((size_t)(b * TT)) * H3 + HH + h * HDIM;
    size_t voff  = ((size_t)(b * TT)) * H3 + 2 * HH + h * HDIM;

#pragma unroll
    for (int i = 0; i < 8; i++) {
        int lin = tid + i * 256;
        int r = lin >> 4, c8 = (lin & 15) * 8;
        cpa16(smem_u32(Qh + r * AST + c8), QKVh + qoffg + (size_t)r * H3 + c8);
        cpa16(smem_u32(Ql + r * AST + c8), QKVl + qoffg + (size_t)r * H3 + c8);
    }

    auto loadKV = [&](int blk, int bufI) {
        ushort_t* kh = KhA + bufI * 64 * AST;
        ushort_t* kl = KlA + bufI * 64 * AST;
        ushort_t* vh = VhA + bufI * 64 * AST;
        ushort_t* vl = VlA + bufI * 64 * AST;
        size_t kb = koff + (size_t)(blk * 64) * H3;
        size_t vb = voff + (size_t)(blk * 64) * H3;
#pragma unroll
        for (int i = 0; i < 4; i++) {
            int lin = tid + i * 256;
            int key = lin >> 4, c8 = (lin & 15) * 8;
            size_t stp = (size_t)key * H3 + c8;
            int so = key * AST + c8;
            cpa16(smem_u32(kh + so), QKVh + kb + stp);
            cpa16(smem_u32(kl + so), QKVl + kb + stp);
            cpa16(smem_u32(vh + so), QKVh + vb + stp);
            cpa16(smem_u32(vl + so), QKVl + vb + stp);
        }
    };

    loadKV(0, 0);
    CP_COMMIT();

    float o[16][4];
#pragma unroll
    for (int i = 0; i < 16; i++)
#pragma unroll
        for (int j = 0; j < 4; j++) o[i][j] = 0.f;

    float mrow0 = -1e30f, mrow1 = -1e30f;
    float lrow0 = 0.f, lrow1 = 0.f;

    int r0 = lane >> 2;
    int cbase = (lane & 3) * 2;
    int qrow0 = qt * 128 + warp * 16 + r0;
    int qrow1 = qrow0 + 8;
    int wmin = qt * 128 + warp * 16;

    const int nblocks = 2 * qt + 2;
    for (int kb = 0; kb < nblocks; kb++) {
        int buf = kb & 1;

        CP_WAIT(0);
        __syncthreads();

        if (kb + 1 < nblocks) loadKV(kb + 1, buf ^ 1);
        CP_COMMIT();

        ushort_t* KhB = KhA + buf * 64 * AST;
        ushort_t* KlB = KlA + buf * 64 * AST;
        ushort_t* VhB = VhA + buf * 64 * AST;
        ushort_t* VlB = VlA + buf * 64 * AST;

        int kbase = kb * 64;
        bool live = (kbase <= wmin + 15);
        if (live) {
            float s[8][4];
#pragma unroll
            for (int i = 0; i < 8; i++)
#pragma unroll
                for (int j = 0; j < 4; j++) s[i][j] = 0.f;

#pragma unroll
            for (int ks = 0; ks < 8; ks++) {
                uint32_t ah[4], al[4];
                int qoff = (warp * 16 + (lane & 15)) * AST + ks * 16 + ((lane >> 4) << 3);
                ldsm_x4(ah, smem_u32(&Qh[qoff]));
                ldsm_x4(al, smem_u32(&Ql[qoff]));
                int nrow_off = ((lane >> 4) << 3) + (lane & 7);
                int kcol = ks * 16 + (((lane >> 3) & 1) << 3);
#pragma unroll
                for (int ntp = 0; ntp < 4; ntp++) {
                    uint32_t bhf[4], blf[4];
                    int koff2 = (ntp * 16 + nrow_off) * AST + kcol;
                    ldsm_x4(bhf, smem_u32(&KhB[koff2]));
                    ldsm_x4(blf, smem_u32(&KlB[koff2]));
                    mma16816(s[2 * ntp], ah, bhf);
                    mma16816(s[2 * ntp], ah, blf);
                    mma16816(s[2 * ntp], al, bhf);
                    mma16816(s[2 * ntp + 1], ah, bhf + 2);
                    mma16816(s[2 * ntp + 1], ah, blf + 2);
                    mma16816(s[2 * ntp + 1], al, bhf + 2);
                }
            }

            if (kbase + 63 > wmin) {
#pragma unroll
                for (int nt = 0; nt < 8; nt++) {
#pragma unroll
                    for (int j = 0; j < 2; j++) {
                        int col = kbase + nt * 8 + cbase + j;
                        if (col > qrow0) s[nt][j] = -1e30f;
                        if (col > qrow1) s[nt][2 + j] = -1e30f;
                    }
                }
            }

            float mx0 = -1e30f, mx1 = -1e30f;
#pragma unroll
            for (int nt = 0; nt < 8; nt++) {
                mx0 = fmaxf(mx0, fmaxf(s[nt][0], s[nt][1]));
                mx1 = fmaxf(mx1, fmaxf(s[nt][2], s[nt][3]));
            }
            mx0 = fmaxf(mx0, __shfl_xor_sync(0xffffffffu, mx0, 1));
            mx0 = fmaxf(mx0, __shfl_xor_sync(0xffffffffu, mx0, 2));
            mx1 = fmaxf(mx1, __shfl_xor_sync(0xffffffffu, mx1, 1));
            mx1 = fmaxf(mx1, __shfl_xor_sync(0xffffffffu, mx1, 2));
            float mn0 = fmaxf(mrow0, mx0), mn1 = fmaxf(mrow1, mx1);
            float c0 = __expf(mrow0 - mn0), c1 = __expf(mrow1 - mn1);
            mrow0 = mn0; mrow1 = mn1;
            float sum0 = 0.f, sum1 = 0.f;
#pragma unroll
            for (int nt = 0; nt < 8; nt++) {
                s[nt][0] = __expf(s[nt][0] - mn0); sum0 += s[nt][0];
                s[nt][1] = __expf(s[nt][1] - mn0); sum0 += s[nt][1];
                s[nt][2] = __expf(s[nt][2] - mn1); sum1 += s[nt][2];
                s[nt][3] = __expf(s[nt][3] - mn1); sum1 += s[nt][3];
            }
            sum0 += __shfl_xor_sync(0xffffffffu, sum0, 1);
            sum0 += __shfl_xor_sync(0xffffffffu, sum0, 2);
            sum1 += __shfl_xor_sync(0xffffffffu, sum1, 1);
            sum1 += __shfl_xor_sync(0xffffffffu, sum1, 2);
            lrow0 = lrow0 * c0 + sum0;
            lrow1 = lrow1 * c1 + sum1;
#pragma unroll
            for (int nt = 0; nt < 16; nt++) {
                o[nt][0] *= c0; o[nt][1] *= c0;
                o[nt][2] *= c1; o[nt][3] *= c1;
            }

#pragma unroll
            for (int ks2 = 0; ks2 < 4; ks2++) {
                uint32_t pah[4], pal[4];
                split2pack(s[2 * ks2][0], s[2 * ks2][1], pah[0], pal[0]);
                split2pack(s[2 * ks2][2], s[2 * ks2][3], pah[1], pal[1]);
                split2pack(s[2 * ks2 + 1][0], s[2 * ks2 + 1][1], pah[2], pal[2]);
                split2pack(s[2 * ks2 + 1][2], s[2 * ks2 + 1][3], pah[3], pal[3]);
                int vrow = ks2 * 16 + (lane & 15);
                int vcol_off = (lane >> 4) << 3;
#pragma unroll
                for (int ntp = 0; ntp < 8; ntp++) {
                    uint32_t vhf[4], vlf[4];
                    int voff2 = vrow * AST + ntp * 16 + vcol_off;
                    ldsm_x4t(vhf, smem_u32(&VhB[voff2]));
                    ldsm_x4t(vlf, smem_u32(&VlB[voff2]));
                    mma16816(o[2 * ntp], pah, vhf);
                    mma16816(o[2 * ntp], pah, vlf);
                    mma16816(o[2 * ntp], pal, vhf);
                    mma16816(o[2 * ntp + 1], pah, vhf + 2);
                    mma16816(o[2 * ntp + 1], pah, vlf + 2);
                    mma16816(o[2 * ntp + 1], pal, vhf + 2);
                }
            }
        }
    }

    float inv0 = 1.f / lrow0, inv1 = 1.f / lrow1;
    size_t obase = ((size_t)(b * TT)) * HH + h * HDIM;
    int grow0 = qt * 128 + warp * 16 + r0;
#pragma unroll
    for (int nt = 0; nt < 16; nt++) {
        int col = nt * 8 + cbase;
        uint32_t hpk, lpk;
        split2pack(o[nt][0] * inv0, o[nt][1] * inv0, hpk, lpk);
        *(uint32_t*)(Ohp + obase + (size_t)grow0 * HH + col) = hpk;
        *(uint32_t*)(Olp + obase + (size_t)grow0 * HH + col) = lpk;
        split2pack(o[nt][2] * inv1, o[nt][3] * inv1, hpk, lpk);
        *(uint32_t*)(Ohp + obase + (size_t)(grow0 + 8) * HH + col) = hpk;
        *(uint32_t*)(Olp + obase + (size_t)(grow0 + 8) * HH + col) = lpk;
    }
}

// ---------------- launch ----------------------------------------------------
extern "C" void kernel_launch(void* const* d_in, const int* in_sizes, int n_in,
                              void* d_out, int out_size)
{
    const float* x   = (const float*)d_in[0];
    const float* wq  = (const float*)d_in[1];
    const float* wk  = (const float*)d_in[2];
    const float* wv  = (const float*)d_in[3];
    const float* wo  = (const float*)d_in[4];
    const float* ln1s = (const float*)d_in[5];
    const float* ln1b = (const float*)d_in[6];
    const float* ln2s = (const float*)d_in[7];
    const float* ln2b = (const float*)d_in[8];
    const float* w1  = (const float*)d_in[9];
    const float* b1  = (const float*)d_in[10];
    const float* w2  = (const float*)d_in[11];
    const float* b2  = (const float*)d_in[12];
    float* out = (float*)d_out;

    ushort_t *hh, *hl, *qkvh, *qkvl, *ath, *atl, *fh, *fl;
    ushort_t *wqkvh, *wqkvl, *woh, *wol, *w1h, *w1l, *w2h, *w2l;
    float *x1;
    cudaGetSymbolAddress((void**)&hh, g_h_hi);     cudaGetSymbolAddress((void**)&hl, g_h_lo);
    cudaGetSymbolAddress((void**)&qkvh, g_qkv_hi); cudaGetSymbolAddress((void**)&qkvl, g_qkv_lo);
    cudaGetSymbolAddress((void**)&ath, g_at_hi);   cudaGetSymbolAddress((void**)&atl, g_at_lo);
    cudaGetSymbolAddress((void**)&fh, g_f_hi);     cudaGetSymbolAddress((void**)&fl, g_f_lo);
    cudaGetSymbolAddress((void**)&wqkvh, g_wqkv_hi); cudaGetSymbolAddress((void**)&wqkvl, g_wqkv_lo);
    cudaGetSymbolAddress((void**)&woh, g_wo_hi);   cudaGetSymbolAddress((void**)&wol, g_wo_lo);
    cudaGetSymbolAddress((void**)&w1h, g_w1_hi);   cudaGetSymbolAddress((void**)&w1l, g_w1_lo);
    cudaGetSymbolAddress((void**)&w2h, g_w2_hi);   cudaGetSymbolAddress((void**)&w2l, g_w2_lo);
    cudaGetSymbolAddress((void**)&x1, g_x1);

    cudaFuncSetAttribute(bgemm_kernel<0,2>, cudaFuncAttributeMaxDynamicSharedMemorySize, GEMM_SMEM);
    cudaFuncSetAttribute(bgemm_kernel<1,0>, cudaFuncAttributeMaxDynamicSharedMemorySize, GEMM_SMEM);
    cudaFuncSetAttribute(bgemm_kernel<2,1>, cudaFuncAttributeMaxDynamicSharedMemorySize, GEMM_SMEM);
    cudaFuncSetAttribute(bgemm_kernel<3,0>, cudaFuncAttributeMaxDynamicSharedMemorySize, GEMM_SMEM);
    const int att_smem = (2 * 128 + 8 * 64) * AST * 2;
    cudaFuncSetAttribute(fattn_kernel, cudaFuncAttributeMaxDynamicSharedMemorySize, att_smem);

    dim3 gQKV(H3 / 128, MM / 128);   // 48 x 32
    dim3 gHH(HH / 128, MM / 128);
    dim3 gFF(FF / 128, MM / 128);
    dim3 blk(256);

    wsplit_qkv_kernel<<<HH * H3 / 1024, 256>>>(wq, wk, wv, wqkvh, wqkvl);
    wsplit_kernel<<<HH * HH / 1024, 256>>>(wo, woh, wol);
    wsplit_kernel<<<HH * FF / 1024, 256>>>(w1, w1h, w1l);
    wsplit_kernel<<<HH * FF / 1024, 256>>>(w2, w2h, w2l);

    ln_kernel<<<MM, 256>>>(x, ln1s, ln1b, hh, hl);
    bgemm_kernel<0,2><<<gQKV, blk, GEMM_SMEM>>>(hh, hl, wqkvh, wqkvl, nullptr, nullptr, nullptr, qkvh, qkvl, MM, H3, HH, 1.f);
    dim3 ga(BB * NHD, TT / 128);
    fattn_kernel<<<ga, 256, att_smem>>>(qkvh, qkvl, ath, atl);
    bgemm_kernel<1,0><<<gHH, blk, GEMM_SMEM>>>(ath, atl, woh, wol, nullptr, x, x1, nullptr, nullptr, MM, HH, HH, 1.f);
    ln_kernel<<<MM, 256>>>(x1, ln2s, ln2b, hh, hl);
    bgemm_kernel<2,1><<<gFF, blk, GEMM_SMEM>>>(hh, hl, w1h, w1l, b1, nullptr, nullptr, fh, fl, MM, FF, HH, 1.f);
    bgemm_kernel<3,0><<<gHH, blk, GEMM_SMEM>>>(fh, fl, w2h, w2l, b2, x1, out, nullptr, nullptr, MM, HH, FF, 1.f);
}